// round 1
// baseline (speedup 1.0000x reference)
#include <cuda_runtime.h>
#include <cstdint>
#include <cstddef>

#define BQ      8192
#define IN_DIM  1024
#define H_DIM   2048
#define OUT_DIM 1024
#define KCAT    4096   // 2*H_DIM

// ---------------- scratch (no allocations allowed) ----------------
__device__ float g_hcat[(size_t)BQ * KCAT];       // [8192, 4096]: [hr | -hi], tf32-rounded
__device__ float g_xr [(size_t)BQ * IN_DIM];      // tf32-rounded x
__device__ float g_Brr[(size_t)H_DIM * IN_DIM];
__device__ float g_Bir[(size_t)H_DIM * IN_DIM];
__device__ float g_Crr[(size_t)OUT_DIM * H_DIM];
__device__ float g_Cir[(size_t)OUT_DIM * H_DIM];
__device__ float g_wr[H_DIM];
__device__ float g_wi[H_DIM];

// ---------------- helpers ----------------
__device__ __forceinline__ float rna_tf32(float x) {
    uint32_t r;
    asm("cvt.rna.tf32.f32 %0, %1;" : "=r"(r) : "f"(x));
    return __uint_as_float(r);
}
__device__ __forceinline__ uint32_t smem_u32(const void* p) {
    return (uint32_t)__cvta_generic_to_shared(p);
}
__device__ __forceinline__ void cp16(uint32_t dst, const void* src) {
    asm volatile("cp.async.cg.shared.global [%0], [%1], 16;" :: "r"(dst), "l"(src));
}
__device__ __forceinline__ void cp_commit() { asm volatile("cp.async.commit_group;"); }
template <int N> __device__ __forceinline__ void cp_wait() {
    asm volatile("cp.async.wait_group %0;" :: "n"(N));
}
__device__ __forceinline__ void ldm4(uint32_t& r0, uint32_t& r1, uint32_t& r2, uint32_t& r3, uint32_t a) {
    asm volatile("ldmatrix.sync.aligned.m8n8.x4.shared.b16 {%0,%1,%2,%3}, [%4];"
                 : "=r"(r0), "=r"(r1), "=r"(r2), "=r"(r3) : "r"(a));
}
__device__ __forceinline__ void mma8(float* c, const uint32_t* a, uint32_t b0, uint32_t b1) {
    asm volatile("mma.sync.aligned.m16n8k8.row.col.f32.tf32.tf32.f32 "
                 "{%0,%1,%2,%3}, {%4,%5,%6,%7}, {%8,%9}, {%0,%1,%2,%3};"
                 : "+f"(c[0]), "+f"(c[1]), "+f"(c[2]), "+f"(c[3])
                 : "r"(a[0]), "r"(a[1]), "r"(a[2]), "r"(a[3]), "r"(b0), "r"(b1));
}

// smem tile: 128 rows x 16 cols, row stride 20 floats (80B) -> ldmatrix conflict-free
#define SST 20

// load one 128x16 fp32 tile (g pre-offset to tile origin), 256 threads, 16B chunks
__device__ __forceinline__ void load_tile(float* s, const float* g, int ld) {
#pragma unroll
    for (int c = 0; c < 2; c++) {
        int idx = threadIdx.x + c * 256;
        int row = idx >> 2;
        int kc  = (idx & 3) << 2;
        cp16(smem_u32(s + row * SST + kc), g + (size_t)row * ld + kc);
    }
}

// one BK=16 compute step for one warp: acc[2][8][4] += A(32x16) * B(64x16)^T
__device__ __forceinline__ void mma_tile(float c[2][8][4], const float* As, const float* Bs,
                                         int wm, int wn, int lane) {
#pragma unroll
    for (int ks = 0; ks < 2; ks++) {
        const int k0 = ks * 8;
        uint32_t af[2][4];
        const int ar = (lane & 7) + ((lane >> 3) & 1) * 8;
        const int ac = k0 + (lane >> 4) * 4;
#pragma unroll
        for (int mi = 0; mi < 2; mi++) {
            uint32_t addr = smem_u32(As + (wm * 32 + mi * 16 + ar) * SST + ac);
            ldm4(af[mi][0], af[mi][1], af[mi][2], af[mi][3], addr);
        }
        const int br = (lane & 7) + ((lane >> 4) ? 8 : 0);
        const int bc = k0 + ((lane >> 3) & 1) * 4;
#pragma unroll
        for (int p = 0; p < 4; p++) {
            uint32_t b0, b1, b2, b3;
            uint32_t addr = smem_u32(Bs + (wn * 64 + p * 16 + br) * SST + bc);
            ldm4(b0, b1, b2, b3, addr);
#pragma unroll
            for (int mi = 0; mi < 2; mi++) {
                mma8(c[mi][2 * p],     af[mi], b0, b1);
                mma8(c[mi][2 * p + 1], af[mi], b2, b3);
            }
        }
    }
}

// ---------------- tiny prep kernels ----------------
__global__ void w_kernel(const float* __restrict__ v_log, const float* __restrict__ theta_log) {
    int h = blockIdx.x * blockDim.x + threadIdx.x;
    if (h < H_DIM) {
        float mag = expf(-expf(v_log[h]));
        float ang = expf(theta_log[h]);
        g_wr[h] = mag * cosf(ang);
        g_wi[h] = mag * sinf(ang);
    }
}

__global__ void round_kernel(const float4* __restrict__ src, float4* __restrict__ dst, int n4) {
    int i = blockIdx.x * blockDim.x + threadIdx.x;
    if (i < n4) {
        float4 v = src[i];
        v.x = rna_tf32(v.x); v.y = rna_tf32(v.y);
        v.z = rna_tf32(v.z); v.w = rna_tf32(v.w);
        dst[i] = v;
    }
}

// ---------------- GEMM1: hcat = [ x@Br^T + hp*wr | -(x@Bi^T + hp*wi) ] ----------------
// grid (64, 32): M=8192, N=4096, K=1024
__global__ void __launch_bounds__(256, 1) g1_kernel(const float* __restrict__ h_prev) {
    __shared__ float As[2][128 * SST];
    __shared__ float Bs[2][128 * SST];
    const int bm = blockIdx.x, bn = blockIdx.y;
    const int tid = threadIdx.x, wid = tid >> 5, lane = tid & 31;
    const int wm = wid >> 1, wn = wid & 1;

    const float* Ag = g_xr + (size_t)bm * 128 * IN_DIM;
    const int n0 = bn * 128;
    const float* Bg = (n0 < H_DIM ? g_Brr : g_Bir) + (size_t)(n0 & (H_DIM - 1)) * IN_DIM;

    float c[2][8][4] = {};

    const int NKT = IN_DIM / 16;  // 64
    load_tile(As[0], Ag, IN_DIM);
    load_tile(Bs[0], Bg, IN_DIM);
    cp_commit();
    for (int t = 0; t < NKT; t++) {
        if (t + 1 < NKT) {
            int st = (t + 1) & 1;
            load_tile(As[st], Ag + (t + 1) * 16, IN_DIM);
            load_tile(Bs[st], Bg + (t + 1) * 16, IN_DIM);
            cp_commit();
            cp_wait<1>();
        } else {
            cp_wait<0>();
        }
        __syncthreads();
        mma_tile(c, As[t & 1], Bs[t & 1], wm, wn, lane);
        __syncthreads();
    }

    // epilogue: add recurrence term, negate imag half, tf32-round, store to hcat
    const int g = lane >> 2, tq = lane & 3;
#pragma unroll
    for (int mi = 0; mi < 2; mi++) {
#pragma unroll
        for (int ni = 0; ni < 8; ni++) {
            int col = n0 + wn * 64 + ni * 8 + 2 * tq;
            int h = col & (H_DIM - 1);
            bool lo = (col < H_DIM);
            float2 w2 = lo ? *(const float2*)(g_wr + h) : *(const float2*)(g_wi + h);
#pragma unroll
            for (int hf = 0; hf < 2; hf++) {
                int row = bm * 128 + wm * 32 + mi * 16 + hf * 8 + g;
                float2 hp = *(const float2*)(h_prev + (size_t)row * H_DIM + h);
                float v0 = c[mi][ni][hf * 2 + 0] + hp.x * w2.x;
                float v1 = c[mi][ni][hf * 2 + 1] + hp.y * w2.y;
                if (!lo) { v0 = -v0; v1 = -v1; }
                float2 o;
                o.x = rna_tf32(v0);
                o.y = rna_tf32(v1);
                *(float2*)(g_hcat + (size_t)row * KCAT + col) = o;
            }
        }
    }
}

// ---------------- GEMM2: out = hcat @ [Cr | Ci]^T ----------------
// grid (64, 8): M=8192, N=1024, K=4096 (k<2048 -> Cr, else Ci)
__global__ void __launch_bounds__(256, 1) g2_kernel(float* __restrict__ out) {
    __shared__ float As[2][128 * SST];
    __shared__ float Bs[2][128 * SST];
    const int bm = blockIdx.x, bn = blockIdx.y;
    const int tid = threadIdx.x, wid = tid >> 5, lane = tid & 31;
    const int wm = wid >> 1, wn = wid & 1;

    const float* Ag = g_hcat + (size_t)bm * 128 * KCAT;
    const int n0 = bn * 128;

    float c[2][8][4] = {};

    const int NKT = KCAT / 16;  // 256
    {
        const float* Bg = g_Crr + (size_t)n0 * H_DIM;  // tile 0: col0 = 0 < H_DIM
        load_tile(As[0], Ag, KCAT);
        load_tile(Bs[0], Bg, H_DIM);
        cp_commit();
    }
    for (int t = 0; t < NKT; t++) {
        if (t + 1 < NKT) {
            int st = (t + 1) & 1;
            int col0 = (t + 1) * 16;
            const float* Bg = (col0 < H_DIM)
                ? g_Crr + (size_t)n0 * H_DIM + col0
                : g_Cir + (size_t)n0 * H_DIM + (col0 - H_DIM);
            load_tile(As[st], Ag + col0, KCAT);
            load_tile(Bs[st], Bg, H_DIM);
            cp_commit();
            cp_wait<1>();
        } else {
            cp_wait<0>();
        }
        __syncthreads();
        mma_tile(c, As[t & 1], Bs[t & 1], wm, wn, lane);
        __syncthreads();
    }

    const int g = lane >> 2, tq = lane & 3;
#pragma unroll
    for (int mi = 0; mi < 2; mi++) {
#pragma unroll
        for (int ni = 0; ni < 8; ni++) {
            int col = n0 + wn * 64 + ni * 8 + 2 * tq;
#pragma unroll
            for (int hf = 0; hf < 2; hf++) {
                int row = bm * 128 + wm * 32 + mi * 16 + hf * 8 + g;
                float2 o;
                o.x = c[mi][ni][hf * 2 + 0];
                o.y = c[mi][ni][hf * 2 + 1];
                *(float2*)(out + (size_t)row * OUT_DIM + col) = o;
            }
        }
    }
}

// ---------------- launch ----------------
extern "C" void kernel_launch(void* const* d_in, const int* in_sizes, int n_in,
                              void* d_out, int out_size) {
    const float* x         = (const float*)d_in[0];
    const float* h_prev    = (const float*)d_in[1];
    const float* Br        = (const float*)d_in[2];
    const float* Bi        = (const float*)d_in[3];
    const float* Cr        = (const float*)d_in[4];
    const float* Ci        = (const float*)d_in[5];
    const float* v_log     = (const float*)d_in[6];
    const float* theta_log = (const float*)d_in[7];

    // resolve device-global scratch addresses (host side)
    float *p_xr, *p_Brr, *p_Bir, *p_Crr, *p_Cir;
    cudaGetSymbolAddress((void**)&p_xr,  g_xr);
    cudaGetSymbolAddress((void**)&p_Brr, g_Brr);
    cudaGetSymbolAddress((void**)&p_Bir, g_Bir);
    cudaGetSymbolAddress((void**)&p_Crr, g_Crr);
    cudaGetSymbolAddress((void**)&p_Cir, g_Cir);

    w_kernel<<<(H_DIM + 255) / 256, 256>>>(v_log, theta_log);

    {   // tf32-round inputs (RN, to kill truncation bias)
        int n4x = BQ * IN_DIM / 4;          // 2M
        int n4b = H_DIM * IN_DIM / 4;       // 512K
        int n4c = OUT_DIM * H_DIM / 4;      // 512K
        round_kernel<<<(n4x + 255) / 256, 256>>>((const float4*)x,  (float4*)p_xr,  n4x);
        round_kernel<<<(n4b + 255) / 256, 256>>>((const float4*)Br, (float4*)p_Brr, n4b);
        round_kernel<<<(n4b + 255) / 256, 256>>>((const float4*)Bi, (float4*)p_Bir, n4b);
        round_kernel<<<(n4c + 255) / 256, 256>>>((const float4*)Cr, (float4*)p_Crr, n4c);
        round_kernel<<<(n4c + 255) / 256, 256>>>((const float4*)Ci, (float4*)p_Cir, n4c);
    }

    g1_kernel<<<dim3(BQ / 128, KCAT / 128), 256>>>(h_prev);
    g2_kernel<<<dim3(BQ / 128, OUT_DIM / 128), 256>>>((float*)d_out);
}

// round 2
// speedup vs baseline: 3.2195x; 3.2195x over previous
#include <cuda_runtime.h>
#include <cstdint>
#include <cstddef>

#define BQ      8192
#define IN_DIM  1024
#define H_DIM   2048
#define OUT_DIM 1024
#define KMAIN   3072   // IN_DIM + H_DIM
#define KFOLD   4096   // 2*H_DIM

// ---------------- scratch (no allocations allowed) ----------------
__device__ float g_xr  [(size_t)BQ * IN_DIM];       // tf32-rounded x
__device__ float g_hpr [(size_t)BQ * H_DIM];        // tf32-rounded h_prev
__device__ float g_Crr [(size_t)OUT_DIM * H_DIM];   // tf32-rounded Cr
__device__ float g_Cir [(size_t)OUT_DIM * H_DIM];   // tf32-rounded Ci
__device__ float g_BrT [(size_t)IN_DIM * H_DIM];    // Br^T, tf32-rounded
__device__ float g_BiTn[(size_t)IN_DIM * H_DIM];    // -Bi^T, tf32-rounded
__device__ float g_E   [(size_t)OUT_DIM * IN_DIM];  // Cr@Br - Ci@Bi, tf32-rounded
__device__ float g_D   [(size_t)OUT_DIM * H_DIM];   // wr.*Cr - wi.*Ci, tf32-rounded
__device__ float g_wr[H_DIM];
__device__ float g_wi[H_DIM];

// ---------------- helpers ----------------
__device__ __forceinline__ float rna_tf32(float x) {
    uint32_t r;
    asm("cvt.rna.tf32.f32 %0, %1;" : "=r"(r) : "f"(x));
    return __uint_as_float(r);
}
__device__ __forceinline__ uint32_t smem_u32(const void* p) {
    return (uint32_t)__cvta_generic_to_shared(p);
}
__device__ __forceinline__ void cp16(uint32_t dst, const void* src) {
    asm volatile("cp.async.cg.shared.global [%0], [%1], 16;" :: "r"(dst), "l"(src));
}
__device__ __forceinline__ void cp_commit() { asm volatile("cp.async.commit_group;"); }
template <int N> __device__ __forceinline__ void cp_wait() {
    asm volatile("cp.async.wait_group %0;" :: "n"(N));
}
__device__ __forceinline__ void ldm4(uint32_t& r0, uint32_t& r1, uint32_t& r2, uint32_t& r3, uint32_t a) {
    asm volatile("ldmatrix.sync.aligned.m8n8.x4.shared.b16 {%0,%1,%2,%3}, [%4];"
                 : "=r"(r0), "=r"(r1), "=r"(r2), "=r"(r3) : "r"(a));
}
__device__ __forceinline__ void mma8(float* c, const uint32_t* a, uint32_t b0, uint32_t b1) {
    asm volatile("mma.sync.aligned.m16n8k8.row.col.f32.tf32.tf32.f32 "
                 "{%0,%1,%2,%3}, {%4,%5,%6,%7}, {%8,%9}, {%0,%1,%2,%3};"
                 : "+f"(c[0]), "+f"(c[1]), "+f"(c[2]), "+f"(c[3])
                 : "r"(a[0]), "r"(a[1]), "r"(a[2]), "r"(a[3]), "r"(b0), "r"(b1));
}

// smem tile: 128 rows x 16 cols, row stride 20 floats -> ldmatrix conflict-free
#define SST 20
#define STAGE_FLOATS (2 * 128 * SST)   // A tile + B tile per stage
#define NSTAGES 3

// load one 128x16 fp32 tile (g pre-offset to tile origin), 256 threads, 16B chunks
__device__ __forceinline__ void load_tile(float* s, const float* g, int ld) {
#pragma unroll
    for (int c = 0; c < 2; c++) {
        int idx = threadIdx.x + c * 256;
        int row = idx >> 2;
        int kc  = (idx & 3) << 2;
        cp16(smem_u32(s + row * SST + kc), g + (size_t)row * ld + kc);
    }
}

// one BK=16 compute step for one warp: acc[2][8][4] += A(32x16) * B(64x16)^T
__device__ __forceinline__ void mma_tile(float c[2][8][4], const float* As, const float* Bs,
                                         int wm, int wn, int lane) {
#pragma unroll
    for (int ks = 0; ks < 2; ks++) {
        const int k0 = ks * 8;
        uint32_t af[2][4];
        const int ar = (lane & 7) + ((lane >> 3) & 1) * 8;
        const int ac = k0 + (lane >> 4) * 4;
#pragma unroll
        for (int mi = 0; mi < 2; mi++) {
            uint32_t addr = smem_u32(As + (wm * 32 + mi * 16 + ar) * SST + ac);
            ldm4(af[mi][0], af[mi][1], af[mi][2], af[mi][3], addr);
        }
        const int br = (lane & 7) + ((lane >> 4) ? 8 : 0);
        const int bc = k0 + ((lane >> 3) & 1) * 4;
#pragma unroll
        for (int p = 0; p < 4; p++) {
            uint32_t b0, b1, b2, b3;
            uint32_t addr = smem_u32(Bs + (wn * 64 + p * 16 + br) * SST + bc);
            ldm4(b0, b1, b2, b3, addr);
#pragma unroll
            for (int mi = 0; mi < 2; mi++) {
                mma8(c[mi][2 * p],     af[mi], b0, b1);
                mma8(c[mi][2 * p + 1], af[mi], b2, b3);
            }
        }
    }
}

// ---------------- prep kernels ----------------
__global__ void w_kernel(const float* __restrict__ v_log, const float* __restrict__ theta_log) {
    int h = blockIdx.x * blockDim.x + threadIdx.x;
    if (h < H_DIM) {
        float mag = expf(-expf(v_log[h]));
        float ang = expf(theta_log[h]);
        g_wr[h] = mag * cosf(ang);
        g_wi[h] = mag * sinf(ang);
    }
}

__global__ void round_kernel(const float4* __restrict__ src, float4* __restrict__ dst, int n4) {
    int i = blockIdx.x * blockDim.x + threadIdx.x;
    if (i < n4) {
        float4 v = src[i];
        v.x = rna_tf32(v.x); v.y = rna_tf32(v.y);
        v.z = rna_tf32(v.z); v.w = rna_tf32(v.w);
        dst[i] = v;
    }
}

// D = rna(wr.*Cr - wi.*Ci), elementwise over [OUT, H]
__global__ void d_kernel(const float4* __restrict__ Cr, const float4* __restrict__ Ci,
                         float4* __restrict__ D) {
    int i = blockIdx.x * blockDim.x + threadIdx.x;   // float4 index
    if (i < OUT_DIM * H_DIM / 4) {
        int h4 = i & (H_DIM / 4 - 1);
        float4 wr = ((const float4*)g_wr)[h4];
        float4 wi = ((const float4*)g_wi)[h4];
        float4 cr = Cr[i], ci = Ci[i];
        float4 o;
        o.x = rna_tf32(wr.x * cr.x - wi.x * ci.x);
        o.y = rna_tf32(wr.y * cr.y - wi.y * ci.y);
        o.z = rna_tf32(wr.z * cr.z - wi.z * ci.z);
        o.w = rna_tf32(wr.w * cr.w - wi.w * ci.w);
        D[i] = o;
    }
}

// transpose [R, C] -> [C, R] with sign and tf32 rounding; block (32,8), grid (C/32, R/32)
__global__ void transpose_kernel(const float* __restrict__ src, float* __restrict__ dst,
                                 int R, int C, float sign) {
    __shared__ float tile[32][33];
    int cx = blockIdx.x * 32 + threadIdx.x;
    int ry = blockIdx.y * 32 + threadIdx.y;
#pragma unroll
    for (int j = 0; j < 32; j += 8)
        tile[threadIdx.y + j][threadIdx.x] = src[(size_t)(ry + j) * C + cx];
    __syncthreads();
    int ox = blockIdx.y * 32 + threadIdx.x;   // output col (= src row)
    int oy = blockIdx.x * 32 + threadIdx.y;   // output row (= src col)
#pragma unroll
    for (int j = 0; j < 32; j += 8)
        dst[(size_t)(oy + j) * R + ox] = rna_tf32(sign * tile[threadIdx.x][threadIdx.y + j]);
}

// ---------------- fold GEMM: E = Cr@Br - Ci@Bi  (M=1024,N=1024,K=4096) ----------------
__global__ void __launch_bounds__(256, 1) fold_kernel() {
    extern __shared__ float smem[];
    const int bm = blockIdx.x, bn = blockIdx.y;
    const int tid = threadIdx.x, wid = tid >> 5, lane = tid & 31;
    const int wm = wid >> 1, wn = wid & 1;
    const int m0 = bm * 128, n0 = bn * 128;

    float c[2][8][4] = {};
    const int NKT = KFOLD / 16;  // 256

#pragma unroll 1
    for (int s = 0; s < 2; s++) {
        int k0 = s * 16;
        load_tile(smem + s * STAGE_FLOATS,               g_Crr + (size_t)m0 * H_DIM + k0, H_DIM);
        load_tile(smem + s * STAGE_FLOATS + 128 * SST,   g_BrT + (size_t)n0 * H_DIM + k0, H_DIM);
        cp_commit();
    }
#pragma unroll 1
    for (int t = 0; t < NKT; t++) {
        if (t + 2 < NKT) cp_wait<1>(); else cp_wait<0>();
        __syncthreads();
        if (t + 2 < NKT) {
            int k0 = (t + 2) * 16;
            float* sb = smem + ((t + 2) % NSTAGES) * STAGE_FLOATS;
            const float* Ag = (k0 < H_DIM) ? g_Crr + (size_t)m0 * H_DIM + k0
                                           : g_Cir + (size_t)m0 * H_DIM + (k0 - H_DIM);
            const float* Bg = (k0 < H_DIM) ? g_BrT  + (size_t)n0 * H_DIM + k0
                                           : g_BiTn + (size_t)n0 * H_DIM + (k0 - H_DIM);
            load_tile(sb, Ag, H_DIM);
            load_tile(sb + 128 * SST, Bg, H_DIM);
            cp_commit();
        }
        const float* st = smem + (t % NSTAGES) * STAGE_FLOATS;
        mma_tile(c, st, st + 128 * SST, wm, wn, lane);
    }

    const int g = lane >> 2, tq = lane & 3;
#pragma unroll
    for (int mi = 0; mi < 2; mi++)
#pragma unroll
        for (int ni = 0; ni < 8; ni++) {
            int col = n0 + wn * 64 + ni * 8 + 2 * tq;
#pragma unroll
            for (int hf = 0; hf < 2; hf++) {
                int row = m0 + wm * 32 + mi * 16 + hf * 8 + g;
                float2 o;
                o.x = rna_tf32(c[mi][ni][hf * 2 + 0]);
                o.y = rna_tf32(c[mi][ni][hf * 2 + 1]);
                *(float2*)(g_E + (size_t)row * IN_DIM + col) = o;
            }
        }
}

// ---------------- main GEMM: out = [x | hp] @ [E | D]^T  (M=8192,N=1024,K=3072) ----------------
__global__ void __launch_bounds__(256, 1) main_kernel(float* __restrict__ out) {
    extern __shared__ float smem[];
    const int bm = blockIdx.x, bn = blockIdx.y;
    const int tid = threadIdx.x, wid = tid >> 5, lane = tid & 31;
    const int wm = wid >> 1, wn = wid & 1;
    const int m0 = bm * 128, n0 = bn * 128;

    float c[2][8][4] = {};
    const int NKT = KMAIN / 16;  // 192

#pragma unroll 1
    for (int s = 0; s < 2; s++) {
        int k0 = s * 16;
        load_tile(smem + s * STAGE_FLOATS,             g_xr + (size_t)m0 * IN_DIM + k0, IN_DIM);
        load_tile(smem + s * STAGE_FLOATS + 128 * SST, g_E  + (size_t)n0 * IN_DIM + k0, IN_DIM);
        cp_commit();
    }
#pragma unroll 1
    for (int t = 0; t < NKT; t++) {
        if (t + 2 < NKT) cp_wait<1>(); else cp_wait<0>();
        __syncthreads();
        if (t + 2 < NKT) {
            int k0 = (t + 2) * 16;
            float* sb = smem + ((t + 2) % NSTAGES) * STAGE_FLOATS;
            if (k0 < IN_DIM) {
                load_tile(sb,             g_xr + (size_t)m0 * IN_DIM + k0, IN_DIM);
                load_tile(sb + 128 * SST, g_E  + (size_t)n0 * IN_DIM + k0, IN_DIM);
            } else {
                int kh = k0 - IN_DIM;
                load_tile(sb,             g_hpr + (size_t)m0 * H_DIM + kh, H_DIM);
                load_tile(sb + 128 * SST, g_D   + (size_t)n0 * H_DIM + kh, H_DIM);
            }
            cp_commit();
        }
        const float* st = smem + (t % NSTAGES) * STAGE_FLOATS;
        mma_tile(c, st, st + 128 * SST, wm, wn, lane);
    }

    const int g = lane >> 2, tq = lane & 3;
#pragma unroll
    for (int mi = 0; mi < 2; mi++)
#pragma unroll
        for (int ni = 0; ni < 8; ni++) {
            int col = n0 + wn * 64 + ni * 8 + 2 * tq;
#pragma unroll
            for (int hf = 0; hf < 2; hf++) {
                int row = m0 + wm * 32 + mi * 16 + hf * 8 + g;
                float2 o;
                o.x = c[mi][ni][hf * 2 + 0];
                o.y = c[mi][ni][hf * 2 + 1];
                *(float2*)(out + (size_t)row * OUT_DIM + col) = o;
            }
        }
}

// ---------------- launch ----------------
extern "C" void kernel_launch(void* const* d_in, const int* in_sizes, int n_in,
                              void* d_out, int out_size) {
    const float* x         = (const float*)d_in[0];
    const float* h_prev    = (const float*)d_in[1];
    const float* Br        = (const float*)d_in[2];
    const float* Bi        = (const float*)d_in[3];
    const float* Cr        = (const float*)d_in[4];
    const float* Ci        = (const float*)d_in[5];
    const float* v_log     = (const float*)d_in[6];
    const float* theta_log = (const float*)d_in[7];

    float *p_xr, *p_hpr, *p_Crr, *p_Cir, *p_BrT, *p_BiTn, *p_D;
    cudaGetSymbolAddress((void**)&p_xr,   g_xr);
    cudaGetSymbolAddress((void**)&p_hpr,  g_hpr);
    cudaGetSymbolAddress((void**)&p_Crr,  g_Crr);
    cudaGetSymbolAddress((void**)&p_Cir,  g_Cir);
    cudaGetSymbolAddress((void**)&p_BrT,  g_BrT);
    cudaGetSymbolAddress((void**)&p_BiTn, g_BiTn);
    cudaGetSymbolAddress((void**)&p_D,    g_D);

    static bool attr_done = false;
    if (!attr_done) {
        int smem_bytes = NSTAGES * STAGE_FLOATS * sizeof(float);  // 61440
        cudaFuncSetAttribute(fold_kernel, cudaFuncAttributeMaxDynamicSharedMemorySize, smem_bytes);
        cudaFuncSetAttribute(main_kernel, cudaFuncAttributeMaxDynamicSharedMemorySize, smem_bytes);
        attr_done = true;
    }
    const int smem_bytes = NSTAGES * STAGE_FLOATS * sizeof(float);

    w_kernel<<<(H_DIM + 255) / 256, 256>>>(v_log, theta_log);

    {   // tf32 RN rounding of GEMM operands
        int n4x = BQ * IN_DIM / 4;
        int n4h = BQ * H_DIM / 4;
        int n4c = OUT_DIM * H_DIM / 4;
        round_kernel<<<(n4x + 255) / 256, 256>>>((const float4*)x,      (float4*)p_xr,  n4x);
        round_kernel<<<(n4h + 255) / 256, 256>>>((const float4*)h_prev, (float4*)p_hpr, n4h);
        round_kernel<<<(n4c + 255) / 256, 256>>>((const float4*)Cr,     (float4*)p_Crr, n4c);
        round_kernel<<<(n4c + 255) / 256, 256>>>((const float4*)Ci,     (float4*)p_Cir, n4c);
    }

    // Br [H, IN] -> BrT [IN, H];  Bi -> -BiT
    transpose_kernel<<<dim3(IN_DIM / 32, H_DIM / 32), dim3(32, 8)>>>(Br, p_BrT,  H_DIM, IN_DIM,  1.0f);
    transpose_kernel<<<dim3(IN_DIM / 32, H_DIM / 32), dim3(32, 8)>>>(Bi, p_BiTn, H_DIM, IN_DIM, -1.0f);

    d_kernel<<<(OUT_DIM * H_DIM / 4 + 255) / 256, 256>>>((const float4*)Cr, (const float4*)Ci,
                                                         (float4*)p_D);

    fold_kernel<<<dim3(OUT_DIM / 128, IN_DIM / 128), 256, smem_bytes>>>();
    main_kernel<<<dim3(BQ / 128, OUT_DIM / 128), 256, smem_bytes>>>((float*)d_out);
}

// round 4
// speedup vs baseline: 12.9520x; 4.0230x over previous
#include <cuda_runtime.h>
#include <cstdint>
#include <cstddef>

#define BQ      8192
#define IN_DIM  1024
#define H_DIM   2048
#define OUT_DIM 1024

#if defined(__CUDA_ARCH_FEAT_SM103_ALL) || defined(__CUDA_ARCH_FEAT_SM100_ALL)
#define TC_OK 1
#else
#define TC_OK 0
#endif

// ---------------- scratch ----------------
__device__ float g_xr  [(size_t)BQ * IN_DIM];
__device__ float g_hpr [(size_t)BQ * H_DIM];
__device__ float g_Crr [(size_t)OUT_DIM * H_DIM];
__device__ float g_Cir [(size_t)OUT_DIM * H_DIM];
__device__ float g_BrT [(size_t)IN_DIM * H_DIM];
__device__ float g_BiTn[(size_t)IN_DIM * H_DIM];
__device__ float g_E   [(size_t)OUT_DIM * IN_DIM];
__device__ float g_D   [(size_t)OUT_DIM * H_DIM];

// ---------------- helpers ----------------
__device__ __forceinline__ float rna_tf32(float x) {
    uint32_t r;
    asm("cvt.rna.tf32.f32 %0, %1;" : "=r"(r) : "f"(x));
    return __uint_as_float(r);
}
__device__ __forceinline__ uint32_t smem_u32(const void* p) {
    return (uint32_t)__cvta_generic_to_shared(p);
}
__device__ __forceinline__ void cp16(uint32_t dst, const void* src) {
    asm volatile("cp.async.cg.shared.global [%0], [%1], 16;" :: "r"(dst), "l"(src));
}
__device__ __forceinline__ void cp_commit() { asm volatile("cp.async.commit_group;"); }
template <int N> __device__ __forceinline__ void cp_wait() {
    asm volatile("cp.async.wait_group %0;" :: "n"(N));
}
__device__ __forceinline__ uint32_t swz(uint32_t off) {   // SW128
    return off ^ ((off >> 3) & 0x70);
}
__device__ __forceinline__ void mbar_init(uint32_t addr, uint32_t cnt) {
    asm volatile("mbarrier.init.shared.b64 [%0], %1;" :: "r"(addr), "r"(cnt) : "memory");
}
__device__ __forceinline__ void mbar_wait(uint32_t addr, uint32_t parity) {
    asm volatile(
        "{\n\t.reg .pred P;\n\t"
        "W%=:\n\t"
        "mbarrier.try_wait.parity.shared::cta.b64 P, [%0], %1, 0x989680;\n\t"
        "@!P bra W%=;\n\t"
        "}" :: "r"(addr), "r"(parity) : "memory");
}
__device__ __forceinline__ void cp_arrive(uint32_t addr) {
    asm volatile("cp.async.mbarrier.arrive.noinc.shared::cta.b64 [%0];" :: "r"(addr) : "memory");
}
// mma.sync fallback helpers
__device__ __forceinline__ void ldm4(uint32_t& r0, uint32_t& r1, uint32_t& r2, uint32_t& r3, uint32_t a) {
    asm volatile("ldmatrix.sync.aligned.m8n8.x4.shared.b16 {%0,%1,%2,%3}, [%4];"
                 : "=r"(r0), "=r"(r1), "=r"(r2), "=r"(r3) : "r"(a));
}
__device__ __forceinline__ void mma8(float* c, const uint32_t* a, uint32_t b0, uint32_t b1) {
    asm volatile("mma.sync.aligned.m16n8k8.row.col.f32.tf32.tf32.f32 "
                 "{%0,%1,%2,%3}, {%4,%5,%6,%7}, {%8,%9}, {%0,%1,%2,%3};"
                 : "+f"(c[0]), "+f"(c[1]), "+f"(c[2]), "+f"(c[3])
                 : "r"(a[0]), "r"(a[1]), "r"(a[2]), "r"(a[3]), "r"(b0), "r"(b1));
}

#define SST 20
#define STAGE_FLOATS (2 * 128 * SST)

__device__ __forceinline__ void load_tile(float* s, const float* g, int ld) {
#pragma unroll
    for (int c = 0; c < 2; c++) {
        int idx = threadIdx.x + c * 256;
        int row = idx >> 2;
        int kc  = (idx & 3) << 2;
        cp16(smem_u32(s + row * SST + kc), g + (size_t)row * ld + kc);
    }
}
__device__ __forceinline__ void mma_tile(float c[2][8][4], const float* As, const float* Bs,
                                         int wm, int wn, int lane) {
#pragma unroll
    for (int ks = 0; ks < 2; ks++) {
        const int k0 = ks * 8;
        uint32_t af[2][4];
        const int ar = (lane & 7) + ((lane >> 3) & 1) * 8;
        const int ac = k0 + (lane >> 4) * 4;
#pragma unroll
        for (int mi = 0; mi < 2; mi++) {
            uint32_t addr = smem_u32(As + (wm * 32 + mi * 16 + ar) * SST + ac);
            ldm4(af[mi][0], af[mi][1], af[mi][2], af[mi][3], addr);
        }
        const int br = (lane & 7) + ((lane >> 4) ? 8 : 0);
        const int bc = k0 + ((lane >> 3) & 1) * 4;
#pragma unroll
        for (int p = 0; p < 4; p++) {
            uint32_t b0, b1, b2, b3;
            uint32_t addr = smem_u32(Bs + (wn * 64 + p * 16 + br) * SST + bc);
            ldm4(b0, b1, b2, b3, addr);
#pragma unroll
            for (int mi = 0; mi < 2; mi++) {
                mma8(c[mi][2 * p],     af[mi], b0, b1);
                mma8(c[mi][2 * p + 1], af[mi], b2, b3);
            }
        }
    }
}

#if TC_OK
__device__ __forceinline__ void tc_commit(uint32_t mbar) {
    asm volatile("tcgen05.commit.cta_group::1.mbarrier::arrive::one.shared::cluster.b64 [%0];"
                 :: "r"(mbar) : "memory");
}
__device__ __forceinline__ void mma_tf32_ss(uint32_t d_tmem, uint64_t a_desc, uint64_t b_desc,
                                            uint32_t idesc, bool enable) {
    uint32_t en = enable ? 1u : 0u;
    asm volatile(
        "{\n\t.reg .pred p;\n\t"
        "setp.ne.u32 p, %4, 0;\n\t"
        "tcgen05.mma.cta_group::1.kind::tf32 [%0], %1, %2, %3, {%5,%5,%5,%5}, p;\n\t}"
        :: "r"(d_tmem), "l"(a_desc), "l"(b_desc), "r"(idesc), "r"(en), "r"(0u) : "memory");
}
__device__ __forceinline__ uint64_t mk_desc(uint32_t addr) {
    return ((uint64_t)2 << 61) | ((uint64_t)1 << 46) | ((uint64_t)64 << 32) |
           ((uint64_t)1 << 16) | (((uint64_t)addr >> 4) & 0x3FFF);
}
#endif

// ---------------- prep kernels ----------------
// One fused rounding pass: x, h_prev, Cr, Ci -> RNA-tf32 scratch copies.
__global__ void prep_kernel(const float4* __restrict__ x, const float4* __restrict__ h,
                            const float4* __restrict__ cr, const float4* __restrict__ ci) {
    const int N1 = BQ * IN_DIM / 4;
    const int N2 = N1 + BQ * H_DIM / 4;
    const int N3 = N2 + OUT_DIM * H_DIM / 4;
    const int N4 = N3 + OUT_DIM * H_DIM / 4;
    int i = blockIdx.x * blockDim.x + threadIdx.x;
    if (i >= N4) return;
    const float4* src; float4* dst; int j = i;
    if (i < N1)      { src = x;  dst = (float4*)g_xr; }
    else if (i < N2) { src = h;  dst = (float4*)g_hpr; j = i - N1; }
    else if (i < N3) { src = cr; dst = (float4*)g_Crr; j = i - N2; }
    else             { src = ci; dst = (float4*)g_Cir; j = i - N3; }
    float4 v = src[j];
    v.x = rna_tf32(v.x); v.y = rna_tf32(v.y);
    v.z = rna_tf32(v.z); v.w = rna_tf32(v.w);
    dst[j] = v;
}

// D = rna(wr.*Cr - wi.*Ci); w recomputed inline (cheap, saves a launch slot)
__global__ void d_kernel(const float4* __restrict__ Cr, const float4* __restrict__ Ci,
                         const float* __restrict__ v_log, const float* __restrict__ theta_log,
                         float4* __restrict__ D) {
    int i = blockIdx.x * blockDim.x + threadIdx.x;
    if (i < OUT_DIM * H_DIM / 4) {
        int h0 = (i & (H_DIM / 4 - 1)) * 4;
        float4 cr = Cr[i], ci = Ci[i];
        float o[4];
        const float* c4r = (const float*)&cr;
        const float* c4i = (const float*)&ci;
#pragma unroll
        for (int k = 0; k < 4; k++) {
            float mag = expf(-expf(v_log[h0 + k]));
            float ang = expf(theta_log[h0 + k]);
            o[k] = rna_tf32(mag * cosf(ang) * c4r[k] - mag * sinf(ang) * c4i[k]);
        }
        D[i] = make_float4(o[0], o[1], o[2], o[3]);
    }
}

__global__ void transpose_kernel(const float* __restrict__ src, float* __restrict__ dst,
                                 int R, int C, float sign) {
    __shared__ float tile[32][33];
    int cx = blockIdx.x * 32 + threadIdx.x;
    int ry = blockIdx.y * 32 + threadIdx.y;
#pragma unroll
    for (int j = 0; j < 32; j += 8)
        tile[threadIdx.y + j][threadIdx.x] = src[(size_t)(ry + j) * C + cx];
    __syncthreads();
    int ox = blockIdx.y * 32 + threadIdx.x;
    int oy = blockIdx.x * 32 + threadIdx.y;
#pragma unroll
    for (int j = 0; j < 32; j += 8)
        dst[(size_t)(oy + j) * R + ox] = rna_tf32(sign * tile[threadIdx.x][threadIdx.y + j]);
}

// ---------------- GEMM: out[128*gx, NTILE*gy] = A @ B^T (k-major, split at KSPLIT) ----------------
template <int NTILE, int NKT, int KSPLIT, int LDA0, int LDA1, int LDB0, int LDB1, bool ROUND>
__global__ void __launch_bounds__(256, 1) gemm_tc(
    const float* __restrict__ A0, const float* __restrict__ A1,
    const float* __restrict__ B0, const float* __restrict__ B1,
    float* __restrict__ out, int ldOut)
{
    extern __shared__ __align__(16) char dsm[];
    const int tid = threadIdx.x;
    const int m0 = blockIdx.x * 128;
    const int n0 = blockIdx.y * NTILE;

#if TC_OK
    constexpr int NS = 4;
    constexpr int ABYTES = 128 * 128;
    constexpr int STAGE  = ABYTES + NTILE * 128;
    const uint32_t sbase = (smem_u32(dsm) + 1023u) & ~1023u;

    __shared__ __align__(8) uint64_t mbar[2 * NS + 1];
    __shared__ uint32_t tmem_slot[1];

    const uint32_t fullA  = smem_u32(&mbar[0]);
    const uint32_t emptyA = smem_u32(&mbar[NS]);
    const uint32_t doneA  = smem_u32(&mbar[2 * NS]);

    if (tid < 32) {
        asm volatile("tcgen05.alloc.cta_group::1.sync.aligned.shared::cta.b32 [%0], %1;"
                     :: "r"(smem_u32(tmem_slot)), "r"((uint32_t)NTILE) : "memory");
    }
    if (tid == 0) {
#pragma unroll
        for (int s = 0; s < NS; s++) {
            mbar_init(fullA  + 8 * s, 128);
            mbar_init(emptyA + 8 * s, 1);
        }
        mbar_init(doneA, 1);
    }
    __syncthreads();
    const uint32_t tmem = tmem_slot[0];

    if (tid < 128) {
        // producers
        for (int u = 0; u < NKT; u++) {
            const int s = u & (NS - 1);
            if (u >= NS) mbar_wait(emptyA + 8 * s, ((u / NS) - 1) & 1);
            const int k0 = u * 32;
            const float* Ag; int lda;
            const float* Bg; int ldb;
            if (k0 < KSPLIT) { Ag = A0 + (size_t)m0 * LDA0 + k0; lda = LDA0; }
            else             { Ag = A1 + (size_t)m0 * LDA1 + (k0 - KSPLIT); lda = LDA1; }
            if (k0 < KSPLIT) { Bg = B0 + (size_t)n0 * LDB0 + k0; ldb = LDB0; }
            else             { Bg = B1 + (size_t)n0 * LDB1 + (k0 - KSPLIT); ldb = LDB1; }
            const uint32_t sa = sbase + s * STAGE;
            const uint32_t sb = sa + ABYTES;
#pragma unroll
            for (int c = 0; c < 8; c++) {
                int i = tid + c * 128;
                int row = i >> 3, kc = i & 7;
                cp16(sa + swz(row * 128 + kc * 16), Ag + (size_t)row * lda + kc * 4);
            }
#pragma unroll
            for (int c = 0; c < NTILE / 16; c++) {
                int i = tid + c * 128;
                int row = i >> 3, kc = i & 7;
                cp16(sb + swz(row * 128 + kc * 16), Bg + (size_t)row * ldb + kc * 4);
            }
            cp_arrive(fullA + 8 * s);
        }
    } else if (tid == 128) {
        // MMA issuer
        asm volatile("tcgen05.fence::after_thread_sync;" ::: "memory");
        const uint32_t idesc = (1u << 4) | (2u << 7) | (2u << 10) |
                               ((uint32_t)(NTILE / 8) << 17) | (8u << 24);
        for (int t = 0; t < NKT; t++) {
            const int s = t & (NS - 1);
            mbar_wait(fullA + 8 * s, (t / NS) & 1);
            asm volatile("fence.proxy.async.shared::cta;" ::: "memory");
            const uint64_t ad = mk_desc(sbase + s * STAGE);
            const uint64_t bd = mk_desc(sbase + s * STAGE + ABYTES);
#pragma unroll
            for (int k = 0; k < 4; k++)
                mma_tf32_ss(tmem, ad + 2 * k, bd + 2 * k, idesc, !(t == 0 && k == 0));
            tc_commit(emptyA + 8 * s);
        }
        tc_commit(doneA);
    }

    // epilogue
    mbar_wait(doneA, 0);
    asm volatile("tcgen05.fence::after_thread_sync;" ::: "memory");

    if (tid < 128) {
        float* orow = out + (size_t)(m0 + tid) * ldOut + n0;
#pragma unroll
        for (int base = 0; base < NTILE; base += 32) {
            uint32_t r[32];
            asm volatile(
                "tcgen05.ld.sync.aligned.32x32b.x32.b32 "
                "{%0,%1,%2,%3,%4,%5,%6,%7,%8,%9,%10,%11,%12,%13,%14,%15,"
                "%16,%17,%18,%19,%20,%21,%22,%23,%24,%25,%26,%27,%28,%29,%30,%31}, [%32];"
                : "=r"(r[0]), "=r"(r[1]), "=r"(r[2]), "=r"(r[3]),
                  "=r"(r[4]), "=r"(r[5]), "=r"(r[6]), "=r"(r[7]),
                  "=r"(r[8]), "=r"(r[9]), "=r"(r[10]), "=r"(r[11]),
                  "=r"(r[12]), "=r"(r[13]), "=r"(r[14]), "=r"(r[15]),
                  "=r"(r[16]), "=r"(r[17]), "=r"(r[18]), "=r"(r[19]),
                  "=r"(r[20]), "=r"(r[21]), "=r"(r[22]), "=r"(r[23]),
                  "=r"(r[24]), "=r"(r[25]), "=r"(r[26]), "=r"(r[27]),
                  "=r"(r[28]), "=r"(r[29]), "=r"(r[30]), "=r"(r[31])
                : "r"(tmem + base));
            asm volatile("tcgen05.wait::ld.sync.aligned;" ::: "memory");
            if (ROUND) {
#pragma unroll
                for (int i = 0; i < 32; i++)
                    r[i] = __float_as_uint(rna_tf32(__uint_as_float(r[i])));
            }
#pragma unroll
            for (int q = 0; q < 8; q++) {
                float4 v;
                v.x = __uint_as_float(r[4 * q + 0]);
                v.y = __uint_as_float(r[4 * q + 1]);
                v.z = __uint_as_float(r[4 * q + 2]);
                v.w = __uint_as_float(r[4 * q + 3]);
                *(float4*)(orow + base + 4 * q) = v;
            }
        }
    }
    asm volatile("tcgen05.fence::before_thread_sync;" ::: "memory");
    __syncthreads();
    if (tid < 32) {
        asm volatile("tcgen05.dealloc.cta_group::1.sync.aligned.b32 %0, %1;"
                     :: "r"(tmem), "r"((uint32_t)NTILE));
    }
#else
    // ---------------- fallback: mma.sync tf32 (3-stage cp.async) ----------------
    float* smf = (float*)dsm;
    const int wid = tid >> 5, lane = tid & 31;
    const int wm = wid >> 1, wn = wid & 1;
    const int NKT16 = NKT * 2;

    for (int nh = 0; nh < NTILE / 128; nh++) {
        const int n0h = n0 + nh * 128;
        float c[2][8][4] = {};
#pragma unroll 1
        for (int s = 0; s < 2; s++) {
            int k0 = s * 16;
            const float* Ag = (k0 < KSPLIT) ? A0 + (size_t)m0 * LDA0 + k0
                                            : A1 + (size_t)m0 * LDA1 + (k0 - KSPLIT);
            int lda = (k0 < KSPLIT) ? LDA0 : LDA1;
            const float* Bg = (k0 < KSPLIT) ? B0 + (size_t)n0h * LDB0 + k0
                                            : B1 + (size_t)n0h * LDB1 + (k0 - KSPLIT);
            int ldb = (k0 < KSPLIT) ? LDB0 : LDB1;
            load_tile(smf + s * STAGE_FLOATS, Ag, lda);
            load_tile(smf + s * STAGE_FLOATS + 128 * SST, Bg, ldb);
            cp_commit();
        }
#pragma unroll 1
        for (int t = 0; t < NKT16; t++) {
            if (t + 2 < NKT16) cp_wait<1>(); else cp_wait<0>();
            __syncthreads();
            if (t + 2 < NKT16) {
                int k0 = (t + 2) * 16;
                float* sb = smf + ((t + 2) % 3) * STAGE_FLOATS;
                const float* Ag = (k0 < KSPLIT) ? A0 + (size_t)m0 * LDA0 + k0
                                                : A1 + (size_t)m0 * LDA1 + (k0 - KSPLIT);
                int lda = (k0 < KSPLIT) ? LDA0 : LDA1;
                const float* Bg = (k0 < KSPLIT) ? B0 + (size_t)n0h * LDB0 + k0
                                                : B1 + (size_t)n0h * LDB1 + (k0 - KSPLIT);
                int ldb = (k0 < KSPLIT) ? LDB0 : LDB1;
                load_tile(sb, Ag, lda);
                load_tile(sb + 128 * SST, Bg, ldb);
                cp_commit();
            }
            const float* st = smf + (t % 3) * STAGE_FLOATS;
            mma_tile(c, st, st + 128 * SST, wm, wn, lane);
        }
        __syncthreads();

        const int g = lane >> 2, tq = lane & 3;
#pragma unroll
        for (int mi = 0; mi < 2; mi++)
#pragma unroll
            for (int ni = 0; ni < 8; ni++) {
                int col = n0h + wn * 64 + ni * 8 + 2 * tq;
#pragma unroll
                for (int hf = 0; hf < 2; hf++) {
                    int row = m0 + wm * 32 + mi * 16 + hf * 8 + g;
                    float2 o;
                    o.x = c[mi][ni][hf * 2 + 0];
                    o.y = c[mi][ni][hf * 2 + 1];
                    if (ROUND) { o.x = rna_tf32(o.x); o.y = rna_tf32(o.y); }
                    *(float2*)(out + (size_t)row * ldOut + col) = o;
                }
            }
    }
#endif
}

// ---------------- launch ----------------
extern "C" void kernel_launch(void* const* d_in, const int* in_sizes, int n_in,
                              void* d_out, int out_size) {
    const float* x         = (const float*)d_in[0];
    const float* h_prev    = (const float*)d_in[1];
    const float* Br        = (const float*)d_in[2];
    const float* Bi        = (const float*)d_in[3];
    const float* Cr        = (const float*)d_in[4];
    const float* Ci        = (const float*)d_in[5];
    const float* v_log     = (const float*)d_in[6];
    const float* theta_log = (const float*)d_in[7];

    float *p_xr, *p_hpr, *p_Crr, *p_Cir, *p_BrT, *p_BiTn, *p_E, *p_D;
    cudaGetSymbolAddress((void**)&p_xr,   g_xr);
    cudaGetSymbolAddress((void**)&p_hpr,  g_hpr);
    cudaGetSymbolAddress((void**)&p_Crr,  g_Crr);
    cudaGetSymbolAddress((void**)&p_Cir,  g_Cir);
    cudaGetSymbolAddress((void**)&p_BrT,  g_BrT);
    cudaGetSymbolAddress((void**)&p_BiTn, g_BiTn);
    cudaGetSymbolAddress((void**)&p_E,    g_E);
    cudaGetSymbolAddress((void**)&p_D,    g_D);

    // fold: E = [Cr|Ci] @ [BrT|-BiT]^T   (M=1024, N=1024, K=4096)
    auto* foldK = gemm_tc<128, 128, 2048, 2048, 2048, 2048, 2048, true>;
    // main: out = [x|hp] @ [E|D]^T       (M=8192, N=1024, K=3072)
    auto* mainK = gemm_tc<256, 96, 1024, 1024, 2048, 1024, 2048, false>;

    const int smem_fold = 4 * (128 * 128 + 128 * 128) + 1024;   // 132 KB
    const int smem_main = 4 * (128 * 128 + 256 * 128) + 1024;   // 197.5 KB
    static bool attr_done = false;
    if (!attr_done) {
        cudaFuncSetAttribute(foldK, cudaFuncAttributeMaxDynamicSharedMemorySize, smem_fold);
        cudaFuncSetAttribute(mainK, cudaFuncAttributeMaxDynamicSharedMemorySize, smem_main);
        attr_done = true;
    }

    {   // launch 0: fused RNA rounding
        int ntot = (BQ * IN_DIM + BQ * H_DIM + 2 * OUT_DIM * H_DIM) / 4;
        prep_kernel<<<(ntot + 255) / 256, 256>>>((const float4*)x, (const float4*)h_prev,
                                                 (const float4*)Cr, (const float4*)Ci);
    }
    // launch 1: D
    d_kernel<<<(OUT_DIM * H_DIM / 4 + 255) / 256, 256>>>((const float4*)Cr, (const float4*)Ci,
                                                         v_log, theta_log, (float4*)p_D);
    // launches 2,3: transposes
    transpose_kernel<<<dim3(IN_DIM / 32, H_DIM / 32), dim3(32, 8)>>>(Br, p_BrT,  H_DIM, IN_DIM,  1.0f);
    transpose_kernel<<<dim3(IN_DIM / 32, H_DIM / 32), dim3(32, 8)>>>(Bi, p_BiTn, H_DIM, IN_DIM, -1.0f);
    // launch 4: fold GEMM
    foldK<<<dim3(OUT_DIM / 128, IN_DIM / 128), 256, smem_fold>>>(p_Crr, p_Cir, p_BrT, p_BiTn,
                                                                 p_E, IN_DIM);
    // launch 5: main GEMM (ncu -s 5 -c 1 captures this)
    mainK<<<dim3(BQ / 128, OUT_DIM / 256), 256, smem_main>>>(p_xr, p_hpr, p_E, p_D,
                                                             (float*)d_out, OUT_DIM);
}

// round 6
// speedup vs baseline: 17.5133x; 1.3522x over previous
#include <cuda_runtime.h>
#include <cstdint>
#include <cstddef>

#define BQ      8192
#define IN_DIM  1024
#define H_DIM   2048
#define OUT_DIM 1024

#if defined(__CUDA_ARCH_FEAT_SM103_ALL) || defined(__CUDA_ARCH_FEAT_SM100_ALL)
#define TC_OK 1
#else
#define TC_OK 0
#endif

// ---------------- scratch ----------------
__device__ float g_Crr [(size_t)OUT_DIM * H_DIM];   // RNA tf32 Cr
__device__ float g_Cir [(size_t)OUT_DIM * H_DIM];   // RNA tf32 Ci
__device__ float g_BrT [(size_t)IN_DIM * H_DIM];    // Br^T, RNA tf32
__device__ float g_BiTn[(size_t)IN_DIM * H_DIM];    // -Bi^T, RNA tf32
__device__ float g_E   [(size_t)OUT_DIM * IN_DIM];  // Cr@Br - Ci@Bi, RNA tf32
__device__ float g_D   [(size_t)OUT_DIM * H_DIM];   // wr.*Cr - wi.*Ci, RNA tf32

// ---------------- helpers ----------------
__device__ __forceinline__ float rna_tf32(float x) {
    uint32_t r;
    asm("cvt.rna.tf32.f32 %0, %1;" : "=r"(r) : "f"(x));
    return __uint_as_float(r);
}
__device__ __forceinline__ uint32_t smem_u32(const void* p) {
    return (uint32_t)__cvta_generic_to_shared(p);
}
__device__ __forceinline__ void cp16(uint32_t dst, const void* src) {
    asm volatile("cp.async.cg.shared.global [%0], [%1], 16;" :: "r"(dst), "l"(src));
}
__device__ __forceinline__ void cp_commit() { asm volatile("cp.async.commit_group;"); }
template <int N> __device__ __forceinline__ void cp_wait() {
    asm volatile("cp.async.wait_group %0;" :: "n"(N));
}
__device__ __forceinline__ uint32_t swz(uint32_t off) {   // SW128
    return off ^ ((off >> 3) & 0x70);
}
__device__ __forceinline__ void mbar_init(uint32_t addr, uint32_t cnt) {
    asm volatile("mbarrier.init.shared.b64 [%0], %1;" :: "r"(addr), "r"(cnt) : "memory");
}
__device__ __forceinline__ void mbar_wait(uint32_t addr, uint32_t parity) {
    asm volatile(
        "{\n\t.reg .pred P;\n\t"
        "W%=:\n\t"
        "mbarrier.try_wait.parity.shared::cta.b64 P, [%0], %1, 0x989680;\n\t"
        "@!P bra W%=;\n\t"
        "}" :: "r"(addr), "r"(parity) : "memory");
}
__device__ __forceinline__ void cp_arrive(uint32_t addr) {
    asm volatile("cp.async.mbarrier.arrive.noinc.shared::cta.b64 [%0];" :: "r"(addr) : "memory");
}
__device__ __forceinline__ void cluster_sync() {
    asm volatile("barrier.cluster.arrive.aligned;" ::: "memory");
    asm volatile("barrier.cluster.wait.aligned;" ::: "memory");
}
__device__ __forceinline__ uint32_t ctarank() {
    uint32_t r;
    asm("mov.u32 %0, %%cluster_ctarank;" : "=r"(r));
    return r;
}
// mma.sync fallback helpers
__device__ __forceinline__ void ldm4(uint32_t& r0, uint32_t& r1, uint32_t& r2, uint32_t& r3, uint32_t a) {
    asm volatile("ldmatrix.sync.aligned.m8n8.x4.shared.b16 {%0,%1,%2,%3}, [%4];"
                 : "=r"(r0), "=r"(r1), "=r"(r2), "=r"(r3) : "r"(a));
}
__device__ __forceinline__ void mma8(float* c, const uint32_t* a, uint32_t b0, uint32_t b1) {
    asm volatile("mma.sync.aligned.m16n8k8.row.col.f32.tf32.tf32.f32 "
                 "{%0,%1,%2,%3}, {%4,%5,%6,%7}, {%8,%9}, {%0,%1,%2,%3};"
                 : "+f"(c[0]), "+f"(c[1]), "+f"(c[2]), "+f"(c[3])
                 : "r"(a[0]), "r"(a[1]), "r"(a[2]), "r"(a[3]), "r"(b0), "r"(b1));
}

#define SST 20
#define STAGE_FLOATS (2 * 128 * SST)

__device__ __forceinline__ void load_tile(float* s, const float* g, int ld) {
#pragma unroll
    for (int c = 0; c < 2; c++) {
        int idx = threadIdx.x + c * 256;
        int row = idx >> 2;
        int kc  = (idx & 3) << 2;
        cp16(smem_u32(s + row * SST + kc), g + (size_t)row * ld + kc);
    }
}
__device__ __forceinline__ void mma_tile(float c[2][8][4], const float* As, const float* Bs,
                                         int wm, int wn, int lane) {
#pragma unroll
    for (int ks = 0; ks < 2; ks++) {
        const int k0 = ks * 8;
        uint32_t af[2][4];
        const int ar = (lane & 7) + ((lane >> 3) & 1) * 8;
        const int ac = k0 + (lane >> 4) * 4;
#pragma unroll
        for (int mi = 0; mi < 2; mi++) {
            uint32_t addr = smem_u32(As + (wm * 32 + mi * 16 + ar) * SST + ac);
            ldm4(af[mi][0], af[mi][1], af[mi][2], af[mi][3], addr);
        }
        const int br = (lane & 7) + ((lane >> 4) ? 8 : 0);
        const int bc = k0 + ((lane >> 3) & 1) * 4;
#pragma unroll
        for (int p = 0; p < 4; p++) {
            uint32_t b0, b1, b2, b3;
            uint32_t addr = smem_u32(Bs + (wn * 64 + p * 16 + br) * SST + bc);
            ldm4(b0, b1, b2, b3, addr);
#pragma unroll
            for (int mi = 0; mi < 2; mi++) {
                mma8(c[mi][2 * p],     af[mi], b0, b1);
                mma8(c[mi][2 * p + 1], af[mi], b2, b3);
            }
        }
    }
}

#if TC_OK
__device__ __forceinline__ void tc_commit(uint32_t mbar) {
    asm volatile("tcgen05.commit.cta_group::1.mbarrier::arrive::one.shared::cluster.b64 [%0];"
                 :: "r"(mbar) : "memory");
}
__device__ __forceinline__ void tc_commit_mc2(uint32_t mbar) {
    asm volatile(
        "tcgen05.commit.cta_group::2.mbarrier::arrive::one.shared::cluster.multicast::cluster.b64 [%0], %1;"
        :: "r"(mbar), "h"((uint16_t)3) : "memory");
}
__device__ __forceinline__ void mma_tf32_ss(uint32_t d_tmem, uint64_t a_desc, uint64_t b_desc,
                                            uint32_t idesc, bool enable) {
    uint32_t en = enable ? 1u : 0u;
    asm volatile(
        "{\n\t.reg .pred p;\n\t"
        "setp.ne.u32 p, %4, 0;\n\t"
        "tcgen05.mma.cta_group::1.kind::tf32 [%0], %1, %2, %3, {%5,%5,%5,%5}, p;\n\t}"
        :: "r"(d_tmem), "l"(a_desc), "l"(b_desc), "r"(idesc), "r"(en), "r"(0u) : "memory");
}
__device__ __forceinline__ void mma_tf32_ss2(uint32_t d_tmem, uint64_t a_desc, uint64_t b_desc,
                                             uint32_t idesc, bool enable) {
    uint32_t en = enable ? 1u : 0u;
    asm volatile(
        "{\n\t.reg .pred p;\n\t"
        "setp.ne.u32 p, %4, 0;\n\t"
        "tcgen05.mma.cta_group::2.kind::tf32 [%0], %1, %2, %3, {%5,%5,%5,%5,%5,%5,%5,%5}, p;\n\t}"
        :: "r"(d_tmem), "l"(a_desc), "l"(b_desc), "r"(idesc), "r"(en), "r"(0u) : "memory");
}
__device__ __forceinline__ uint64_t mk_desc(uint32_t addr) {
    return ((uint64_t)2 << 61) | ((uint64_t)1 << 46) | ((uint64_t)64 << 32) |
           ((uint64_t)1 << 16) | (((uint64_t)addr >> 4) & 0x3FFF);
}
// epilogue: one x32 LDTM (warp reads its own subpartition)
__device__ __forceinline__ void ldtm32(uint32_t* r, uint32_t addr) {
    asm volatile(
        "tcgen05.ld.sync.aligned.32x32b.x32.b32 "
        "{%0,%1,%2,%3,%4,%5,%6,%7,%8,%9,%10,%11,%12,%13,%14,%15,"
        "%16,%17,%18,%19,%20,%21,%22,%23,%24,%25,%26,%27,%28,%29,%30,%31}, [%32];"
        : "=r"(r[0]), "=r"(r[1]), "=r"(r[2]), "=r"(r[3]),
          "=r"(r[4]), "=r"(r[5]), "=r"(r[6]), "=r"(r[7]),
          "=r"(r[8]), "=r"(r[9]), "=r"(r[10]), "=r"(r[11]),
          "=r"(r[12]), "=r"(r[13]), "=r"(r[14]), "=r"(r[15]),
          "=r"(r[16]), "=r"(r[17]), "=r"(r[18]), "=r"(r[19]),
          "=r"(r[20]), "=r"(r[21]), "=r"(r[22]), "=r"(r[23]),
          "=r"(r[24]), "=r"(r[25]), "=r"(r[26]), "=r"(r[27]),
          "=r"(r[28]), "=r"(r[29]), "=r"(r[30]), "=r"(r[31])
        : "r"(addr));
    asm volatile("tcgen05.wait::ld.sync.aligned;" ::: "memory");
}
#endif

// ---------------- prep kernels ----------------
__global__ void prep_kernel(const float4* __restrict__ cr, const float4* __restrict__ ci) {
    const int N1 = OUT_DIM * H_DIM / 4;
    int i = blockIdx.x * blockDim.x + threadIdx.x;
    if (i >= 2 * N1) return;
    const float4* src = (i < N1) ? cr : ci;
    float4* dst = (i < N1) ? (float4*)g_Crr : (float4*)g_Cir;
    int j = (i < N1) ? i : i - N1;
    float4 v = src[j];
    v.x = rna_tf32(v.x); v.y = rna_tf32(v.y);
    v.z = rna_tf32(v.z); v.w = rna_tf32(v.w);
    dst[j] = v;
}

__global__ void d_kernel(const float4* __restrict__ Cr, const float4* __restrict__ Ci,
                         const float* __restrict__ v_log, const float* __restrict__ theta_log,
                         float4* __restrict__ D) {
    int i = blockIdx.x * blockDim.x + threadIdx.x;
    if (i < OUT_DIM * H_DIM / 4) {
        int h0 = (i & (H_DIM / 4 - 1)) * 4;
        float4 cr = Cr[i], ci = Ci[i];
        float o[4];
        const float* c4r = (const float*)&cr;
        const float* c4i = (const float*)&ci;
#pragma unroll
        for (int k = 0; k < 4; k++) {
            float mag = expf(-expf(v_log[h0 + k]));
            float ang = expf(theta_log[h0 + k]);
            o[k] = rna_tf32(mag * cosf(ang) * c4r[k] - mag * sinf(ang) * c4i[k]);
        }
        D[i] = make_float4(o[0], o[1], o[2], o[3]);
    }
}

__global__ void transpose_kernel(const float* __restrict__ src, float* __restrict__ dst,
                                 int R, int C, float sign) {
    __shared__ float tile[32][33];
    int cx = blockIdx.x * 32 + threadIdx.x;
    int ry = blockIdx.y * 32 + threadIdx.y;
#pragma unroll
    for (int j = 0; j < 32; j += 8)
        tile[threadIdx.y + j][threadIdx.x] = src[(size_t)(ry + j) * C + cx];
    __syncthreads();
    int ox = blockIdx.y * 32 + threadIdx.x;
    int oy = blockIdx.x * 32 + threadIdx.y;
#pragma unroll
    for (int j = 0; j < 32; j += 8)
        dst[(size_t)(oy + j) * R + ox] = rna_tf32(sign * tile[threadIdx.x][threadIdx.y + j]);
}

// ---------------- cg1 GEMM (fold): out[128*gx, NTILE*gy] = A @ B^T ----------------
template <int NTILE, int NKT, int KSPLIT, int LDA0, int LDA1, int LDB0, int LDB1, bool ROUND>
__global__ void __launch_bounds__(256, 1) gemm_tc(
    const float* __restrict__ A0, const float* __restrict__ A1,
    const float* __restrict__ B0, const float* __restrict__ B1,
    float* __restrict__ out, int ldOut)
{
    extern __shared__ __align__(16) char dsm[];
    const int tid = threadIdx.x;
    const int m0 = blockIdx.x * 128;
    const int n0 = blockIdx.y * NTILE;

#if TC_OK
    constexpr int NS = 4;
    constexpr int ABYTES = 128 * 128;
    constexpr int STAGE  = ABYTES + NTILE * 128;
    const uint32_t sbase = (smem_u32(dsm) + 1023u) & ~1023u;

    __shared__ __align__(8) uint64_t mbar[2 * NS + 1];
    __shared__ uint32_t tmem_slot[1];

    const uint32_t fullA  = smem_u32(&mbar[0]);
    const uint32_t emptyA = smem_u32(&mbar[NS]);
    const uint32_t doneA  = smem_u32(&mbar[2 * NS]);

    if (tid < 32) {
        asm volatile("tcgen05.alloc.cta_group::1.sync.aligned.shared::cta.b32 [%0], %1;"
                     :: "r"(smem_u32(tmem_slot)), "r"((uint32_t)NTILE) : "memory");
    }
    if (tid == 0) {
#pragma unroll
        for (int s = 0; s < NS; s++) {
            mbar_init(fullA  + 8 * s, 128);
            mbar_init(emptyA + 8 * s, 1);
        }
        mbar_init(doneA, 1);
    }
    __syncthreads();
    const uint32_t tmem = tmem_slot[0];

    if (tid < 128) {
        for (int u = 0; u < NKT; u++) {
            const int s = u & (NS - 1);
            if (u >= NS) mbar_wait(emptyA + 8 * s, ((u / NS) - 1) & 1);
            const int k0 = u * 32;
            const float* Ag; int lda;
            const float* Bg; int ldb;
            if (k0 < KSPLIT) { Ag = A0 + (size_t)m0 * LDA0 + k0; lda = LDA0; }
            else             { Ag = A1 + (size_t)m0 * LDA1 + (k0 - KSPLIT); lda = LDA1; }
            if (k0 < KSPLIT) { Bg = B0 + (size_t)n0 * LDB0 + k0; ldb = LDB0; }
            else             { Bg = B1 + (size_t)n0 * LDB1 + (k0 - KSPLIT); ldb = LDB1; }
            const uint32_t sa = sbase + s * STAGE;
            const uint32_t sb = sa + ABYTES;
#pragma unroll
            for (int c = 0; c < 8; c++) {
                int i = tid + c * 128;
                int row = i >> 3, kc = i & 7;
                cp16(sa + swz(row * 128 + kc * 16), Ag + (size_t)row * lda + kc * 4);
            }
#pragma unroll
            for (int c = 0; c < NTILE / 16; c++) {
                int i = tid + c * 128;
                int row = i >> 3, kc = i & 7;
                cp16(sb + swz(row * 128 + kc * 16), Bg + (size_t)row * ldb + kc * 4);
            }
            cp_arrive(fullA + 8 * s);
        }
    } else if (tid == 128) {
        asm volatile("tcgen05.fence::after_thread_sync;" ::: "memory");
        const uint32_t idesc = (1u << 4) | (2u << 7) | (2u << 10) |
                               ((uint32_t)(NTILE / 8) << 17) | (8u << 24);
        for (int t = 0; t < NKT; t++) {
            const int s = t & (NS - 1);
            mbar_wait(fullA + 8 * s, (t / NS) & 1);
            asm volatile("fence.proxy.async.shared::cta;" ::: "memory");
            const uint64_t ad = mk_desc(sbase + s * STAGE);
            const uint64_t bd = mk_desc(sbase + s * STAGE + ABYTES);
#pragma unroll
            for (int k = 0; k < 4; k++)
                mma_tf32_ss(tmem, ad + 2 * k, bd + 2 * k, idesc, !(t == 0 && k == 0));
            tc_commit(emptyA + 8 * s);
        }
        tc_commit(doneA);
    }

    mbar_wait(doneA, 0);
    asm volatile("tcgen05.fence::after_thread_sync;" ::: "memory");

    if (tid < 128) {
        float* orow = out + (size_t)(m0 + tid) * ldOut + n0;
#pragma unroll
        for (int base = 0; base < NTILE; base += 32) {
            uint32_t r[32];
            ldtm32(r, tmem + base);
            if (ROUND) {
#pragma unroll
                for (int i = 0; i < 32; i++)
                    r[i] = __float_as_uint(rna_tf32(__uint_as_float(r[i])));
            }
#pragma unroll
            for (int q = 0; q < 8; q++) {
                float4 v;
                v.x = __uint_as_float(r[4 * q + 0]);
                v.y = __uint_as_float(r[4 * q + 1]);
                v.z = __uint_as_float(r[4 * q + 2]);
                v.w = __uint_as_float(r[4 * q + 3]);
                *(float4*)(orow + base + 4 * q) = v;
            }
        }
    }
    asm volatile("tcgen05.fence::before_thread_sync;" ::: "memory");
    __syncthreads();
    if (tid < 32) {
        asm volatile("tcgen05.dealloc.cta_group::1.sync.aligned.b32 %0, %1;"
                     :: "r"(tmem), "r"((uint32_t)NTILE));
    }
#else
    float* smf = (float*)dsm;
    const int wid = tid >> 5, lane = tid & 31;
    const int wm = wid >> 1, wn = wid & 1;
    const int NKT16 = NKT * 2;

    for (int nh = 0; nh < NTILE / 128; nh++) {
        const int n0h = n0 + nh * 128;
        float c[2][8][4] = {};
#pragma unroll 1
        for (int s = 0; s < 2; s++) {
            int k0 = s * 16;
            const float* Ag = (k0 < KSPLIT) ? A0 + (size_t)m0 * LDA0 + k0
                                            : A1 + (size_t)m0 * LDA1 + (k0 - KSPLIT);
            int lda = (k0 < KSPLIT) ? LDA0 : LDA1;
            const float* Bg = (k0 < KSPLIT) ? B0 + (size_t)n0h * LDB0 + k0
                                            : B1 + (size_t)n0h * LDB1 + (k0 - KSPLIT);
            int ldb = (k0 < KSPLIT) ? LDB0 : LDB1;
            load_tile(smf + s * STAGE_FLOATS, Ag, lda);
            load_tile(smf + s * STAGE_FLOATS + 128 * SST, Bg, ldb);
            cp_commit();
        }
#pragma unroll 1
        for (int t = 0; t < NKT16; t++) {
            if (t + 2 < NKT16) cp_wait<1>(); else cp_wait<0>();
            __syncthreads();
            if (t + 2 < NKT16) {
                int k0 = (t + 2) * 16;
                float* sb = smf + ((t + 2) % 3) * STAGE_FLOATS;
                const float* Ag = (k0 < KSPLIT) ? A0 + (size_t)m0 * LDA0 + k0
                                                : A1 + (size_t)m0 * LDA1 + (k0 - KSPLIT);
                int lda = (k0 < KSPLIT) ? LDA0 : LDA1;
                const float* Bg = (k0 < KSPLIT) ? B0 + (size_t)n0h * LDB0 + k0
                                                : B1 + (size_t)n0h * LDB1 + (k0 - KSPLIT);
                int ldb = (k0 < KSPLIT) ? LDB0 : LDB1;
                load_tile(sb, Ag, lda);
                load_tile(sb + 128 * SST, Bg, ldb);
                cp_commit();
            }
            const float* st = smf + (t % 3) * STAGE_FLOATS;
            mma_tile(c, st, st + 128 * SST, wm, wn, lane);
        }
        __syncthreads();

        const int g = lane >> 2, tq = lane & 3;
#pragma unroll
        for (int mi = 0; mi < 2; mi++)
#pragma unroll
            for (int ni = 0; ni < 8; ni++) {
                int col = n0h + wn * 64 + ni * 8 + 2 * tq;
#pragma unroll
                for (int hf = 0; hf < 2; hf++) {
                    int row = m0 + wm * 32 + mi * 16 + hf * 8 + g;
                    float2 o;
                    o.x = c[mi][ni][hf * 2 + 0];
                    o.y = c[mi][ni][hf * 2 + 1];
                    if (ROUND) { o.x = rna_tf32(o.x); o.y = rna_tf32(o.y); }
                    *(float2*)(out + (size_t)row * ldOut + col) = o;
                }
            }
    }
#endif
}

// ---------------- cg2 main GEMM: pair tile M=256 x N=512, K split at KSPLIT ----------------
// grid (2*MPAIRS, NGROUPS), cluster (2,1,1). Per CTA: 128 A rows + 128 B rows per region.
template <int NKT, int KSPLIT, int LDA0, int LDA1, int LDB0, int LDB1>
__global__ void __launch_bounds__(256, 1) __cluster_dims__(2, 1, 1)
gemm_2cta(const float* __restrict__ A0, const float* __restrict__ A1,
          const float* __restrict__ B0, const float* __restrict__ B1,
          float* __restrict__ out, int ldOut)
{
    extern __shared__ __align__(16) char dsm[];
    const int tid = threadIdx.x;

#if TC_OK
    constexpr int NS = 4;
    constexpr int TILE16K = 16384;          // 128 rows x 128 B
    constexpr int STAGE = 3 * TILE16K;      // A + Breg0-half + Breg1-half
    const uint32_t sbase = (smem_u32(dsm) + 1023u) & ~1023u;

    __shared__ __align__(8) uint64_t mbar[3 * NS + 1];
    __shared__ uint32_t tmem_slot[1];

    const uint32_t rank = ctarank();
    const int m0 = (blockIdx.x >> 1) * 256 + (int)rank * 128;  // this CTA's A rows
    const int n0 = blockIdx.y * 512;                           // pair's N window

    const uint32_t fullL  = smem_u32(&mbar[0]);        // local cp.async completion (128)
    const uint32_t full2  = smem_u32(&mbar[NS]);       // leader: both CTAs ready (2)
    const uint32_t emptyA = smem_u32(&mbar[2 * NS]);   // stage consumed (1, multicast)
    const uint32_t doneA  = smem_u32(&mbar[3 * NS]);   // all MMA done (1, multicast)

    if (tid < 32) {
        asm volatile("tcgen05.alloc.cta_group::2.sync.aligned.shared::cta.b32 [%0], %1;"
                     :: "r"(smem_u32(tmem_slot)), "r"(512u) : "memory");
    }
    if (tid == 0) {
#pragma unroll
        for (int s = 0; s < NS; s++) {
            mbar_init(fullL  + 8 * s, 128);
            mbar_init(full2  + 8 * s, 2);
            mbar_init(emptyA + 8 * s, 1);
        }
        mbar_init(doneA, 1);
    }
    __syncthreads();
    const uint32_t tmem = tmem_slot[0];
    cluster_sync();   // all barriers visible cluster-wide before any cross-CTA arrive

    if (tid < 128) {
        // ---------------- producers ----------------
        for (int u = 0; u < NKT; u++) {
            const int s = u & (NS - 1);
            if (u >= NS) mbar_wait(emptyA + 8 * s, ((u / NS) - 1) & 1);
            const int k0 = u * 32;
            const float* Asrc; int lda;
            const float* Bsel; int ldb; int koff;
            if (k0 < KSPLIT) { Asrc = A0 + (size_t)m0 * LDA0 + k0; lda = LDA0;
                               Bsel = B0; ldb = LDB0; koff = k0; }
            else             { Asrc = A1 + (size_t)m0 * LDA1 + (k0 - KSPLIT); lda = LDA1;
                               Bsel = B1; ldb = LDB1; koff = k0 - KSPLIT; }
            const uint32_t sa = sbase + s * STAGE;
#pragma unroll
            for (int c = 0; c < 8; c++) {   // A half-tile: 128 rows x 128 B
                int i = tid + c * 128;
                int row = i >> 3, kc = i & 7;
                cp16(sa + swz(row * 128 + kc * 16), Asrc + (size_t)row * lda + kc * 4);
            }
#pragma unroll
            for (int r = 0; r < 2; r++) {   // B halves of regions 0 and 1
                const float* Bg = Bsel + (size_t)(n0 + r * 256 + (int)rank * 128) * ldb + koff;
                const uint32_t sb = sa + TILE16K + r * TILE16K;
#pragma unroll
                for (int c = 0; c < 8; c++) {
                    int i = tid + c * 128;
                    int row = i >> 3, kc = i & 7;
                    cp16(sb + swz(row * 128 + kc * 16), Bg + (size_t)row * ldb + kc * 4);
                }
            }
            cp_arrive(fullL + 8 * s);
        }
    } else if (tid == 128) {
        // ---------------- forwarder: local ready -> leader's full2 ----------------
        for (int t = 0; t < NKT; t++) {
            const int s = t & (NS - 1);
            mbar_wait(fullL + 8 * s, (t / NS) & 1);
            asm volatile("fence.proxy.async;" ::: "memory");
            asm volatile(
                "{\n\t.reg .b32 ra;\n\t"
                "mapa.shared::cluster.u32 ra, %0, %1;\n\t"
                "mbarrier.arrive.shared::cluster.b64 _, [ra];\n\t}"
                :: "r"(full2 + 8 * s), "r"(0) : "memory");
        }
    } else if (tid == 160 && rank == 0) {
        // ---------------- MMA issuer (leader) ----------------
        asm volatile("tcgen05.fence::after_thread_sync;" ::: "memory");
        const uint32_t idesc = (1u << 4) | (2u << 7) | (2u << 10) |
                               ((256u / 8) << 17) | ((256u / 16) << 24);
        for (int t = 0; t < NKT; t++) {
            const int s = t & (NS - 1);
            mbar_wait(full2 + 8 * s, (t / NS) & 1);
            const uint64_t ad = mk_desc(sbase + s * STAGE);
#pragma unroll
            for (int r = 0; r < 2; r++) {
                const uint64_t bd = mk_desc(sbase + s * STAGE + TILE16K + r * TILE16K);
#pragma unroll
                for (int k = 0; k < 4; k++)
                    mma_tf32_ss2(tmem + r * 256, ad + 2 * k, bd + 2 * k, idesc,
                                 !(t == 0 && k == 0));
            }
            tc_commit_mc2(emptyA + 8 * s);
        }
        tc_commit_mc2(doneA);
    }

    // ---------------- epilogue: each CTA stores its 128 rows x 512 cols ----------------
    mbar_wait(doneA, 0);
    asm volatile("tcgen05.fence::after_thread_sync;" ::: "memory");

    if (tid < 128) {
        float* orow = out + (size_t)(m0 + tid) * ldOut + n0;
#pragma unroll
        for (int base = 0; base < 512; base += 32) {
            uint32_t r[32];
            ldtm32(r, tmem + base);
#pragma unroll
            for (int q = 0; q < 8; q++) {
                float4 v;
                v.x = __uint_as_float(r[4 * q + 0]);
                v.y = __uint_as_float(r[4 * q + 1]);
                v.z = __uint_as_float(r[4 * q + 2]);
                v.w = __uint_as_float(r[4 * q + 3]);
                *(float4*)(orow + base + 4 * q) = v;
            }
        }
    }
    asm volatile("tcgen05.fence::before_thread_sync;" ::: "memory");
    __syncthreads();
    cluster_sync();
    if (tid < 32) {
        asm volatile("tcgen05.relinquish_alloc_permit.cta_group::2.sync.aligned;");
        asm volatile("tcgen05.dealloc.cta_group::2.sync.aligned.b32 %0, %1;"
                     :: "r"(tmem), "r"(512u));
    }
    cluster_sync();
#else
    // ---------------- fallback: mma.sync, each CTA computes its 128 rows x 512 cols ----------------
    float* smf = (float*)dsm;
    const int m0 = blockIdx.x * 128;
    const int n0 = blockIdx.y * 512;
    const int wid = tid >> 5, lane = tid & 31;
    const int wm = wid >> 1, wn = wid & 1;
    const int NKT16 = NKT * 2;

    for (int nh = 0; nh < 4; nh++) {
        const int n0h = n0 + nh * 128;
        float c[2][8][4] = {};
#pragma unroll 1
        for (int s = 0; s < 2; s++) {
            int k0 = s * 16;
            const float* Ag = (k0 < KSPLIT) ? A0 + (size_t)m0 * LDA0 + k0
                                            : A1 + (size_t)m0 * LDA1 + (k0 - KSPLIT);
            int lda = (k0 < KSPLIT) ? LDA0 : LDA1;
            const float* Bg = (k0 < KSPLIT) ? B0 + (size_t)n0h * LDB0 + k0
                                            : B1 + (size_t)n0h * LDB1 + (k0 - KSPLIT);
            int ldb = (k0 < KSPLIT) ? LDB0 : LDB1;
            load_tile(smf + s * STAGE_FLOATS, Ag, lda);
            load_tile(smf + s * STAGE_FLOATS + 128 * SST, Bg, ldb);
            cp_commit();
        }
#pragma unroll 1
        for (int t = 0; t < NKT16; t++) {
            if (t + 2 < NKT16) cp_wait<1>(); else cp_wait<0>();
            __syncthreads();
            if (t + 2 < NKT16) {
                int k0 = (t + 2) * 16;
                float* sb = smf + ((t + 2) % 3) * STAGE_FLOATS;
                const float* Ag = (k0 < KSPLIT) ? A0 + (size_t)m0 * LDA0 + k0
                                                : A1 + (size_t)m0 * LDA1 + (k0 - KSPLIT);
                int lda = (k0 < KSPLIT) ? LDA0 : LDA1;
                const float* Bg = (k0 < KSPLIT) ? B0 + (size_t)n0h * LDB0 + k0
                                                : B1 + (size_t)n0h * LDB1 + (k0 - KSPLIT);
                int ldb = (k0 < KSPLIT) ? LDB0 : LDB1;
                load_tile(sb, Ag, lda);
                load_tile(sb + 128 * SST, Bg, ldb);
                cp_commit();
            }
            const float* st = smf + (t % 3) * STAGE_FLOATS;
            mma_tile(c, st, st + 128 * SST, wm, wn, lane);
        }
        __syncthreads();

        const int g = lane >> 2, tq = lane & 3;
#pragma unroll
        for (int mi = 0; mi < 2; mi++)
#pragma unroll
            for (int ni = 0; ni < 8; ni++) {
                int col = n0h + wn * 64 + ni * 8 + 2 * tq;
#pragma unroll
                for (int hf = 0; hf < 2; hf++) {
                    int row = m0 + wm * 32 + mi * 16 + hf * 8 + g;
                    float2 o;
                    o.x = c[mi][ni][hf * 2 + 0];
                    o.y = c[mi][ni][hf * 2 + 1];
                    *(float2*)(out + (size_t)row * ldOut + col) = o;
                }
            }
    }
#endif
}

// ---------------- launch ----------------
extern "C" void kernel_launch(void* const* d_in, const int* in_sizes, int n_in,
                              void* d_out, int out_size) {
    const float* x         = (const float*)d_in[0];
    const float* h_prev    = (const float*)d_in[1];
    const float* Br        = (const float*)d_in[2];
    const float* Bi        = (const float*)d_in[3];
    const float* Cr        = (const float*)d_in[4];
    const float* Ci        = (const float*)d_in[5];
    const float* v_log     = (const float*)d_in[6];
    const float* theta_log = (const float*)d_in[7];

    float *p_Crr, *p_Cir, *p_BrT, *p_BiTn, *p_E, *p_D;
    cudaGetSymbolAddress((void**)&p_Crr,  g_Crr);
    cudaGetSymbolAddress((void**)&p_Cir,  g_Cir);
    cudaGetSymbolAddress((void**)&p_BrT,  g_BrT);
    cudaGetSymbolAddress((void**)&p_BiTn, g_BiTn);
    cudaGetSymbolAddress((void**)&p_E,    g_E);
    cudaGetSymbolAddress((void**)&p_D,    g_D);

    // fold: E = [Cr|Ci] @ [BrT|-BiT]^T   (M=1024, N=1024, K=4096)
    auto* foldK = gemm_tc<128, 128, 2048, 2048, 2048, 2048, 2048, true>;
    // main: out = [x|hp] @ [E|D]^T       (pair M=256, N=512; M=8192, N=1024, K=3072)
    auto* mainK = gemm_2cta<96, 1024, 1024, 2048, 1024, 2048>;

    const int smem_fold = 4 * (128 * 128 + 128 * 128) + 1024;   // 132 KB
    const int smem_main = 4 * (3 * 16384) + 1024;               // 197632 B
    cudaFuncSetAttribute(foldK, cudaFuncAttributeMaxDynamicSharedMemorySize, smem_fold);
    cudaFuncSetAttribute(mainK, cudaFuncAttributeMaxDynamicSharedMemorySize, smem_main);

    // launch 0: RNA rounding of Cr, Ci
    {
        int ntot = 2 * OUT_DIM * H_DIM / 4;
        prep_kernel<<<(ntot + 255) / 256, 256>>>((const float4*)Cr, (const float4*)Ci);
    }
    // launch 1: D = rna(wr.*Cr - wi.*Ci)
    d_kernel<<<(OUT_DIM * H_DIM / 4 + 255) / 256, 256>>>((const float4*)Cr, (const float4*)Ci,
                                                         v_log, theta_log, (float4*)p_D);
    // launches 2,3: BrT / -BiT (RNA rounded)
    transpose_kernel<<<dim3(IN_DIM / 32, H_DIM / 32), dim3(32, 8)>>>(Br, p_BrT,  H_DIM, IN_DIM,  1.0f);
    transpose_kernel<<<dim3(IN_DIM / 32, H_DIM / 32), dim3(32, 8)>>>(Bi, p_BiTn, H_DIM, IN_DIM, -1.0f);
    // launch 4: fold GEMM
    foldK<<<dim3(OUT_DIM / 128, IN_DIM / 128), 256, smem_fold>>>(p_Crr, p_Cir, p_BrT, p_BiTn,
                                                                 p_E, IN_DIM);
    // launch 5: main GEMM — grid (64, 2) = 32 m-pairs x 2 n-groups, cluster (2,1,1)
    mainK<<<dim3(2 * (BQ / 256), OUT_DIM / 512), 256, smem_main>>>(x, h_prev, p_E, p_D,
                                                                   (float*)d_out, OUT_DIM);
}

// round 7
// speedup vs baseline: 18.2381x; 1.0414x over previous
#include <cuda_runtime.h>
#include <cstdint>
#include <cstddef>

#define BQ      8192
#define IN_DIM  1024
#define H_DIM   2048
#define OUT_DIM 1024

#if defined(__CUDA_ARCH_FEAT_SM103_ALL) || defined(__CUDA_ARCH_FEAT_SM100_ALL)
#define TC_OK 1
#else
#define TC_OK 0
#endif

// ---------------- scratch ----------------
__device__ float g_Crr [(size_t)OUT_DIM * H_DIM];   // RNA tf32 Cr
__device__ float g_Cir [(size_t)OUT_DIM * H_DIM];   // RNA tf32 Ci
__device__ float g_BrT [(size_t)IN_DIM * H_DIM];    // Br^T, RNA tf32
__device__ float g_BiTn[(size_t)IN_DIM * H_DIM];    // -Bi^T, RNA tf32
__device__ float g_E   [(size_t)OUT_DIM * IN_DIM];  // Cr@Br - Ci@Bi, RNA tf32
__device__ float g_D   [(size_t)OUT_DIM * H_DIM];   // wr.*Cr - wi.*Ci, RNA tf32

// ---------------- helpers ----------------
__device__ __forceinline__ float rna_tf32(float x) {
    uint32_t r;
    asm("cvt.rna.tf32.f32 %0, %1;" : "=r"(r) : "f"(x));
    return __uint_as_float(r);
}
__device__ __forceinline__ uint32_t smem_u32(const void* p) {
    return (uint32_t)__cvta_generic_to_shared(p);
}
__device__ __forceinline__ void cp16(uint32_t dst, const void* src) {
    asm volatile("cp.async.cg.shared.global [%0], [%1], 16;" :: "r"(dst), "l"(src));
}
__device__ __forceinline__ void cp_commit() { asm volatile("cp.async.commit_group;"); }
template <int N> __device__ __forceinline__ void cp_wait() {
    asm volatile("cp.async.wait_group %0;" :: "n"(N));
}
__device__ __forceinline__ uint32_t swz(uint32_t off) {   // SW128
    return off ^ ((off >> 3) & 0x70);
}
__device__ __forceinline__ void mbar_init(uint32_t addr, uint32_t cnt) {
    asm volatile("mbarrier.init.shared.b64 [%0], %1;" :: "r"(addr), "r"(cnt) : "memory");
}
__device__ __forceinline__ void mbar_wait(uint32_t addr, uint32_t parity) {
    asm volatile(
        "{\n\t.reg .pred P;\n\t"
        "W%=:\n\t"
        "mbarrier.try_wait.parity.shared::cta.b64 P, [%0], %1, 0x989680;\n\t"
        "@!P bra W%=;\n\t"
        "}" :: "r"(addr), "r"(parity) : "memory");
}
__device__ __forceinline__ void cp_arrive(uint32_t addr) {
    asm volatile("cp.async.mbarrier.arrive.noinc.shared::cta.b64 [%0];" :: "r"(addr) : "memory");
}
__device__ __forceinline__ void cluster_sync() {
    asm volatile("barrier.cluster.arrive.aligned;" ::: "memory");
    asm volatile("barrier.cluster.wait.aligned;" ::: "memory");
}
__device__ __forceinline__ uint32_t ctarank() {
    uint32_t r;
    asm("mov.u32 %0, %%cluster_ctarank;" : "=r"(r));
    return r;
}
__device__ __forceinline__ void gdc_wait() {   // PDL: wait for predecessor kernel
    asm volatile("griddepcontrol.wait;" ::: "memory");
}
// mma.sync fallback helpers
__device__ __forceinline__ void ldm4(uint32_t& r0, uint32_t& r1, uint32_t& r2, uint32_t& r3, uint32_t a) {
    asm volatile("ldmatrix.sync.aligned.m8n8.x4.shared.b16 {%0,%1,%2,%3}, [%4];"
                 : "=r"(r0), "=r"(r1), "=r"(r2), "=r"(r3) : "r"(a));
}
__device__ __forceinline__ void mma8(float* c, const uint32_t* a, uint32_t b0, uint32_t b1) {
    asm volatile("mma.sync.aligned.m16n8k8.row.col.f32.tf32.tf32.f32 "
                 "{%0,%1,%2,%3}, {%4,%5,%6,%7}, {%8,%9}, {%0,%1,%2,%3};"
                 : "+f"(c[0]), "+f"(c[1]), "+f"(c[2]), "+f"(c[3])
                 : "r"(a[0]), "r"(a[1]), "r"(a[2]), "r"(a[3]), "r"(b0), "r"(b1));
}

#define SST 20
#define STAGE_FLOATS (2 * 128 * SST)

__device__ __forceinline__ void load_tile(float* s, const float* g, int ld) {
#pragma unroll
    for (int c = 0; c < 2; c++) {
        int idx = threadIdx.x + c * 256;
        int row = idx >> 2;
        int kc  = (idx & 3) << 2;
        cp16(smem_u32(s + row * SST + kc), g + (size_t)row * ld + kc);
    }
}
__device__ __forceinline__ void mma_tile(float c[2][8][4], const float* As, const float* Bs,
                                         int wm, int wn, int lane) {
#pragma unroll
    for (int ks = 0; ks < 2; ks++) {
        const int k0 = ks * 8;
        uint32_t af[2][4];
        const int ar = (lane & 7) + ((lane >> 3) & 1) * 8;
        const int ac = k0 + (lane >> 4) * 4;
#pragma unroll
        for (int mi = 0; mi < 2; mi++) {
            uint32_t addr = smem_u32(As + (wm * 32 + mi * 16 + ar) * SST + ac);
            ldm4(af[mi][0], af[mi][1], af[mi][2], af[mi][3], addr);
        }
        const int br = (lane & 7) + ((lane >> 4) ? 8 : 0);
        const int bc = k0 + ((lane >> 3) & 1) * 4;
#pragma unroll
        for (int p = 0; p < 4; p++) {
            uint32_t b0, b1, b2, b3;
            uint32_t addr = smem_u32(Bs + (wn * 64 + p * 16 + br) * SST + bc);
            ldm4(b0, b1, b2, b3, addr);
#pragma unroll
            for (int mi = 0; mi < 2; mi++) {
                mma8(c[mi][2 * p],     af[mi], b0, b1);
                mma8(c[mi][2 * p + 1], af[mi], b2, b3);
            }
        }
    }
}

#if TC_OK
__device__ __forceinline__ void tc_commit(uint32_t mbar) {
    asm volatile("tcgen05.commit.cta_group::1.mbarrier::arrive::one.shared::cluster.b64 [%0];"
                 :: "r"(mbar) : "memory");
}
__device__ __forceinline__ void tc_commit_mc2(uint32_t mbar) {
    asm volatile(
        "tcgen05.commit.cta_group::2.mbarrier::arrive::one.shared::cluster.multicast::cluster.b64 [%0], %1;"
        :: "r"(mbar), "h"((uint16_t)3) : "memory");
}
__device__ __forceinline__ void mma_tf32_ss(uint32_t d_tmem, uint64_t a_desc, uint64_t b_desc,
                                            uint32_t idesc, bool enable) {
    uint32_t en = enable ? 1u : 0u;
    asm volatile(
        "{\n\t.reg .pred p;\n\t"
        "setp.ne.u32 p, %4, 0;\n\t"
        "tcgen05.mma.cta_group::1.kind::tf32 [%0], %1, %2, %3, {%5,%5,%5,%5}, p;\n\t}"
        :: "r"(d_tmem), "l"(a_desc), "l"(b_desc), "r"(idesc), "r"(en), "r"(0u) : "memory");
}
__device__ __forceinline__ void mma_tf32_ss2(uint32_t d_tmem, uint64_t a_desc, uint64_t b_desc,
                                             uint32_t idesc, bool enable) {
    uint32_t en = enable ? 1u : 0u;
    asm volatile(
        "{\n\t.reg .pred p;\n\t"
        "setp.ne.u32 p, %4, 0;\n\t"
        "tcgen05.mma.cta_group::2.kind::tf32 [%0], %1, %2, %3, {%5,%5,%5,%5,%5,%5,%5,%5}, p;\n\t}"
        :: "r"(d_tmem), "l"(a_desc), "l"(b_desc), "r"(idesc), "r"(en), "r"(0u) : "memory");
}
__device__ __forceinline__ uint64_t mk_desc(uint32_t addr) {
    return ((uint64_t)2 << 61) | ((uint64_t)1 << 46) | ((uint64_t)64 << 32) |
           ((uint64_t)1 << 16) | (((uint64_t)addr >> 4) & 0x3FFF);
}
__device__ __forceinline__ void ldtm32(uint32_t* r, uint32_t addr) {
    asm volatile(
        "tcgen05.ld.sync.aligned.32x32b.x32.b32 "
        "{%0,%1,%2,%3,%4,%5,%6,%7,%8,%9,%10,%11,%12,%13,%14,%15,"
        "%16,%17,%18,%19,%20,%21,%22,%23,%24,%25,%26,%27,%28,%29,%30,%31}, [%32];"
        : "=r"(r[0]), "=r"(r[1]), "=r"(r[2]), "=r"(r[3]),
          "=r"(r[4]), "=r"(r[5]), "=r"(r[6]), "=r"(r[7]),
          "=r"(r[8]), "=r"(r[9]), "=r"(r[10]), "=r"(r[11]),
          "=r"(r[12]), "=r"(r[13]), "=r"(r[14]), "=r"(r[15]),
          "=r"(r[16]), "=r"(r[17]), "=r"(r[18]), "=r"(r[19]),
          "=r"(r[20]), "=r"(r[21]), "=r"(r[22]), "=r"(r[23]),
          "=r"(r[24]), "=r"(r[25]), "=r"(r[26]), "=r"(r[27]),
          "=r"(r[28]), "=r"(r[29]), "=r"(r[30]), "=r"(r[31])
        : "r"(addr));
    asm volatile("tcgen05.wait::ld.sync.aligned;" ::: "memory");
}
#endif

// ---------------- merged prep: transposes + Cr/Ci rounding + D, one kernel ----------------
// grid 10240 x 256: [0,2048) BrT, [2048,4096) BiTn, [4096,8192) round Cr/Ci, [8192,10240) D
__global__ void prep_all(const float* __restrict__ Br, const float* __restrict__ Bi,
                         const float4* __restrict__ Cr4, const float4* __restrict__ Ci4,
                         const float* __restrict__ v_log, const float* __restrict__ theta_log) {
    const int b = blockIdx.x;
    if (b < 4096) {
        __shared__ float tile[32][33];
        const float* src = (b < 2048) ? Br : Bi;
        float* dst = (b < 2048) ? g_BrT : g_BiTn;
        const float sign = (b < 2048) ? 1.0f : -1.0f;
        const int lb = b & 2047;
        const int bx = lb & 31;    // over IN/32 = 32
        const int by = lb >> 5;    // over H/32 = 64
        const int tx = threadIdx.x & 31, ty = threadIdx.x >> 5;   // (32, 8)
        const int cx = bx * 32 + tx;
        const int ry = by * 32 + ty;
#pragma unroll
        for (int j = 0; j < 32; j += 8)
            tile[ty + j][tx] = src[(size_t)(ry + j) * IN_DIM + cx];
        __syncthreads();
        const int ox = by * 32 + tx;
        const int oy = bx * 32 + ty;
#pragma unroll
        for (int j = 0; j < 32; j += 8)
            dst[(size_t)(oy + j) * H_DIM + ox] = rna_tf32(sign * tile[tx][ty + j]);
    } else if (b < 8192) {
        const int N1 = OUT_DIM * H_DIM / 4;   // 524288
        int i = (b - 4096) * 256 + threadIdx.x;
        const float4* src = (i < N1) ? Cr4 : Ci4;
        float4* dst = (i < N1) ? (float4*)g_Crr : (float4*)g_Cir;
        int j = (i < N1) ? i : i - N1;
        float4 v = src[j];
        v.x = rna_tf32(v.x); v.y = rna_tf32(v.y);
        v.z = rna_tf32(v.z); v.w = rna_tf32(v.w);
        dst[j] = v;
    } else {
        int i = (b - 8192) * 256 + threadIdx.x;   // float4 index over [OUT, H]
        int h0 = (i & (H_DIM / 4 - 1)) * 4;
        float4 cr = Cr4[i], ci = Ci4[i];
        float o[4];
        const float* c4r = (const float*)&cr;
        const float* c4i = (const float*)&ci;
#pragma unroll
        for (int k = 0; k < 4; k++) {
            float mag = expf(-expf(v_log[h0 + k]));
            float ang = expf(theta_log[h0 + k]);
            o[k] = rna_tf32(mag * cosf(ang) * c4r[k] - mag * sinf(ang) * c4i[k]);
        }
        ((float4*)g_D)[i] = make_float4(o[0], o[1], o[2], o[3]);
    }
}

// ---------------- cg1 GEMM (fold): out[128*gx, NTILE*gy] = A @ B^T ----------------
template <int NTILE, int NKT, int KSPLIT, int LDA0, int LDA1, int LDB0, int LDB1, bool ROUND>
__global__ void __launch_bounds__(256, 1) gemm_tc(
    const float* __restrict__ A0, const float* __restrict__ A1,
    const float* __restrict__ B0, const float* __restrict__ B1,
    float* __restrict__ out, int ldOut)
{
    extern __shared__ __align__(16) char dsm[];
    const int tid = threadIdx.x;
    const int m0 = blockIdx.x * 128;
    const int n0 = blockIdx.y * NTILE;

#if TC_OK
    constexpr int NS = 4;
    constexpr int ABYTES = 128 * 128;
    constexpr int STAGE  = ABYTES + NTILE * 128;
    const uint32_t sbase = (smem_u32(dsm) + 1023u) & ~1023u;

    __shared__ __align__(8) uint64_t mbar[2 * NS + 1];
    __shared__ uint32_t tmem_slot[1];

    const uint32_t fullA  = smem_u32(&mbar[0]);
    const uint32_t emptyA = smem_u32(&mbar[NS]);
    const uint32_t doneA  = smem_u32(&mbar[2 * NS]);

    if (tid < 32) {
        asm volatile("tcgen05.alloc.cta_group::1.sync.aligned.shared::cta.b32 [%0], %1;"
                     :: "r"(smem_u32(tmem_slot)), "r"((uint32_t)NTILE) : "memory");
    }
    if (tid == 0) {
#pragma unroll
        for (int s = 0; s < NS; s++) {
            mbar_init(fullA  + 8 * s, 128);
            mbar_init(emptyA + 8 * s, 1);
        }
        mbar_init(doneA, 1);
    }
    __syncthreads();
    const uint32_t tmem = tmem_slot[0];

    if (tid < 128) {
        for (int u = 0; u < NKT; u++) {
            const int s = u & (NS - 1);
            if (u >= NS) mbar_wait(emptyA + 8 * s, ((u / NS) - 1) & 1);
            const int k0 = u * 32;
            const float* Ag; int lda;
            const float* Bg; int ldb;
            if (k0 < KSPLIT) { Ag = A0 + (size_t)m0 * LDA0 + k0; lda = LDA0; }
            else             { Ag = A1 + (size_t)m0 * LDA1 + (k0 - KSPLIT); lda = LDA1; }
            if (k0 < KSPLIT) { Bg = B0 + (size_t)n0 * LDB0 + k0; ldb = LDB0; }
            else             { Bg = B1 + (size_t)n0 * LDB1 + (k0 - KSPLIT); ldb = LDB1; }
            const uint32_t sa = sbase + s * STAGE;
            const uint32_t sb = sa + ABYTES;
#pragma unroll
            for (int c = 0; c < 8; c++) {
                int i = tid + c * 128;
                int row = i >> 3, kc = i & 7;
                cp16(sa + swz(row * 128 + kc * 16), Ag + (size_t)row * lda + kc * 4);
            }
#pragma unroll
            for (int c = 0; c < NTILE / 16; c++) {
                int i = tid + c * 128;
                int row = i >> 3, kc = i & 7;
                cp16(sb + swz(row * 128 + kc * 16), Bg + (size_t)row * ldb + kc * 4);
            }
            cp_arrive(fullA + 8 * s);
        }
    } else if (tid == 128) {
        asm volatile("tcgen05.fence::after_thread_sync;" ::: "memory");
        const uint32_t idesc = (1u << 4) | (2u << 7) | (2u << 10) |
                               ((uint32_t)(NTILE / 8) << 17) | (8u << 24);
        for (int t = 0; t < NKT; t++) {
            const int s = t & (NS - 1);
            mbar_wait(fullA + 8 * s, (t / NS) & 1);
            asm volatile("fence.proxy.async.shared::cta;" ::: "memory");
            const uint64_t ad = mk_desc(sbase + s * STAGE);
            const uint64_t bd = mk_desc(sbase + s * STAGE + ABYTES);
#pragma unroll
            for (int k = 0; k < 4; k++)
                mma_tf32_ss(tmem, ad + 2 * k, bd + 2 * k, idesc, !(t == 0 && k == 0));
            tc_commit(emptyA + 8 * s);
        }
        tc_commit(doneA);
    }

    mbar_wait(doneA, 0);
    asm volatile("tcgen05.fence::after_thread_sync;" ::: "memory");

    if (tid < 128) {
        float* orow = out + (size_t)(m0 + tid) * ldOut + n0;
#pragma unroll
        for (int base = 0; base < NTILE; base += 32) {
            uint32_t r[32];
            ldtm32(r, tmem + base);
            if (ROUND) {
#pragma unroll
                for (int i = 0; i < 32; i++)
                    r[i] = __float_as_uint(rna_tf32(__uint_as_float(r[i])));
            }
#pragma unroll
            for (int q = 0; q < 8; q++) {
                float4 v;
                v.x = __uint_as_float(r[4 * q + 0]);
                v.y = __uint_as_float(r[4 * q + 1]);
                v.z = __uint_as_float(r[4 * q + 2]);
                v.w = __uint_as_float(r[4 * q + 3]);
                *(float4*)(orow + base + 4 * q) = v;
            }
        }
    }
    asm volatile("tcgen05.fence::before_thread_sync;" ::: "memory");
    __syncthreads();
    if (tid < 32) {
        asm volatile("tcgen05.dealloc.cta_group::1.sync.aligned.b32 %0, %1;"
                     :: "r"(tmem), "r"((uint32_t)NTILE));
    }
#else
    float* smf = (float*)dsm;
    const int wid = tid >> 5, lane = tid & 31;
    const int wm = wid >> 1, wn = wid & 1;
    const int NKT16 = NKT * 2;

    for (int nh = 0; nh < NTILE / 128; nh++) {
        const int n0h = n0 + nh * 128;
        float c[2][8][4] = {};
#pragma unroll 1
        for (int s = 0; s < 2; s++) {
            int k0 = s * 16;
            const float* Ag = (k0 < KSPLIT) ? A0 + (size_t)m0 * LDA0 + k0
                                            : A1 + (size_t)m0 * LDA1 + (k0 - KSPLIT);
            int lda = (k0 < KSPLIT) ? LDA0 : LDA1;
            const float* Bg = (k0 < KSPLIT) ? B0 + (size_t)n0h * LDB0 + k0
                                            : B1 + (size_t)n0h * LDB1 + (k0 - KSPLIT);
            int ldb = (k0 < KSPLIT) ? LDB0 : LDB1;
            load_tile(smf + s * STAGE_FLOATS, Ag, lda);
            load_tile(smf + s * STAGE_FLOATS + 128 * SST, Bg, ldb);
            cp_commit();
        }
#pragma unroll 1
        for (int t = 0; t < NKT16; t++) {
            if (t + 2 < NKT16) cp_wait<1>(); else cp_wait<0>();
            __syncthreads();
            if (t + 2 < NKT16) {
                int k0 = (t + 2) * 16;
                float* sb = smf + ((t + 2) % 3) * STAGE_FLOATS;
                const float* Ag = (k0 < KSPLIT) ? A0 + (size_t)m0 * LDA0 + k0
                                                : A1 + (size_t)m0 * LDA1 + (k0 - KSPLIT);
                int lda = (k0 < KSPLIT) ? LDA0 : LDA1;
                const float* Bg = (k0 < KSPLIT) ? B0 + (size_t)n0h * LDB0 + k0
                                                : B1 + (size_t)n0h * LDB1 + (k0 - KSPLIT);
                int ldb = (k0 < KSPLIT) ? LDB0 : LDB1;
                load_tile(sb, Ag, lda);
                load_tile(sb + 128 * SST, Bg, ldb);
                cp_commit();
            }
            const float* st = smf + (t % 3) * STAGE_FLOATS;
            mma_tile(c, st, st + 128 * SST, wm, wn, lane);
        }
        __syncthreads();

        const int g = lane >> 2, tq = lane & 3;
#pragma unroll
        for (int mi = 0; mi < 2; mi++)
#pragma unroll
            for (int ni = 0; ni < 8; ni++) {
                int col = n0h + wn * 64 + ni * 8 + 2 * tq;
#pragma unroll
                for (int hf = 0; hf < 2; hf++) {
                    int row = m0 + wm * 32 + mi * 16 + hf * 8 + g;
                    float2 o;
                    o.x = c[mi][ni][hf * 2 + 0];
                    o.y = c[mi][ni][hf * 2 + 1];
                    if (ROUND) { o.x = rna_tf32(o.x); o.y = rna_tf32(o.y); }
                    *(float2*)(out + (size_t)row * ldOut + col) = o;
                }
            }
    }
#endif
}

// ---------------- cg2 main GEMM: pair tile M=256 x N=512, K split at KSPLIT ----------------
// K region 0 = [A0|B0] (no fold dependency), region 1 = [A1|B1] (E — gated by griddepcontrol.wait)
template <int NKT, int KSPLIT, int LDA0, int LDA1, int LDB0, int LDB1>
__global__ void __launch_bounds__(256, 1) __cluster_dims__(2, 1, 1)
gemm_2cta(const float* __restrict__ A0, const float* __restrict__ A1,
          const float* __restrict__ B0, const float* __restrict__ B1,
          float* __restrict__ out, int ldOut)
{
    extern __shared__ __align__(16) char dsm[];
    const int tid = threadIdx.x;

#if TC_OK
    constexpr int NS = 4;
    constexpr int TILE16K = 16384;
    constexpr int STAGE = 3 * TILE16K;
    const uint32_t sbase = (smem_u32(dsm) + 1023u) & ~1023u;

    __shared__ __align__(8) uint64_t mbar[3 * NS + 1];
    __shared__ uint32_t tmem_slot[1];

    const uint32_t rank = ctarank();
    const int m0 = (blockIdx.x >> 1) * 256 + (int)rank * 128;
    const int n0 = blockIdx.y * 512;

    const uint32_t fullL  = smem_u32(&mbar[0]);
    const uint32_t full2  = smem_u32(&mbar[NS]);
    const uint32_t emptyA = smem_u32(&mbar[2 * NS]);
    const uint32_t doneA  = smem_u32(&mbar[3 * NS]);

    if (tid < 32) {
        asm volatile("tcgen05.alloc.cta_group::2.sync.aligned.shared::cta.b32 [%0], %1;"
                     :: "r"(smem_u32(tmem_slot)), "r"(512u) : "memory");
    }
    if (tid == 0) {
#pragma unroll
        for (int s = 0; s < NS; s++) {
            mbar_init(fullL  + 8 * s, 128);
            mbar_init(full2  + 8 * s, 2);
            mbar_init(emptyA + 8 * s, 1);
        }
        mbar_init(doneA, 1);
    }
    __syncthreads();
    const uint32_t tmem = tmem_slot[0];
    cluster_sync();

    if (tid < 128) {
        // ---------------- producers ----------------
        for (int u = 0; u < NKT; u++) {
            const int s = u & (NS - 1);
            if (u >= NS) mbar_wait(emptyA + 8 * s, ((u / NS) - 1) & 1);
            const int k0 = u * 32;
            if (k0 == KSPLIT) gdc_wait();   // entering E region: wait for fold kernel
            const float* Asrc; int lda;
            const float* Bsel; int ldb; int koff;
            if (k0 < KSPLIT) { Asrc = A0 + (size_t)m0 * LDA0 + k0; lda = LDA0;
                               Bsel = B0; ldb = LDB0; koff = k0; }
            else             { Asrc = A1 + (size_t)m0 * LDA1 + (k0 - KSPLIT); lda = LDA1;
                               Bsel = B1; ldb = LDB1; koff = k0 - KSPLIT; }
            const uint32_t sa = sbase + s * STAGE;
#pragma unroll
            for (int c = 0; c < 8; c++) {
                int i = tid + c * 128;
                int row = i >> 3, kc = i & 7;
                cp16(sa + swz(row * 128 + kc * 16), Asrc + (size_t)row * lda + kc * 4);
            }
#pragma unroll
            for (int r = 0; r < 2; r++) {
                const float* Bg = Bsel + (size_t)(n0 + r * 256 + (int)rank * 128) * ldb + koff;
                const uint32_t sb = sa + TILE16K + r * TILE16K;
#pragma unroll
                for (int c = 0; c < 8; c++) {
                    int i = tid + c * 128;
                    int row = i >> 3, kc = i & 7;
                    cp16(sb + swz(row * 128 + kc * 16), Bg + (size_t)row * ldb + kc * 4);
                }
            }
            cp_arrive(fullL + 8 * s);
        }
    } else if (tid == 128) {
        // ---------------- forwarder ----------------
        for (int t = 0; t < NKT; t++) {
            const int s = t & (NS - 1);
            mbar_wait(fullL + 8 * s, (t / NS) & 1);
            asm volatile("fence.proxy.async;" ::: "memory");
            asm volatile(
                "{\n\t.reg .b32 ra;\n\t"
                "mapa.shared::cluster.u32 ra, %0, %1;\n\t"
                "mbarrier.arrive.shared::cluster.b64 _, [ra];\n\t}"
                :: "r"(full2 + 8 * s), "r"(0) : "memory");
        }
    } else if (tid == 160 && rank == 0) {
        // ---------------- MMA issuer (leader) ----------------
        asm volatile("tcgen05.fence::after_thread_sync;" ::: "memory");
        const uint32_t idesc = (1u << 4) | (2u << 7) | (2u << 10) |
                               ((256u / 8) << 17) | ((256u / 16) << 24);
        for (int t = 0; t < NKT; t++) {
            const int s = t & (NS - 1);
            mbar_wait(full2 + 8 * s, (t / NS) & 1);
            const uint64_t ad = mk_desc(sbase + s * STAGE);
#pragma unroll
            for (int r = 0; r < 2; r++) {
                const uint64_t bd = mk_desc(sbase + s * STAGE + TILE16K + r * TILE16K);
#pragma unroll
                for (int k = 0; k < 4; k++)
                    mma_tf32_ss2(tmem + r * 256, ad + 2 * k, bd + 2 * k, idesc,
                                 !(t == 0 && k == 0));
            }
            tc_commit_mc2(emptyA + 8 * s);
        }
        tc_commit_mc2(doneA);
    }

    // ---------------- epilogue ----------------
    mbar_wait(doneA, 0);
    asm volatile("tcgen05.fence::after_thread_sync;" ::: "memory");

    if (tid < 128) {
        float* orow = out + (size_t)(m0 + tid) * ldOut + n0;
#pragma unroll
        for (int base = 0; base < 512; base += 32) {
            uint32_t r[32];
            ldtm32(r, tmem + base);
#pragma unroll
            for (int q = 0; q < 8; q++) {
                float4 v;
                v.x = __uint_as_float(r[4 * q + 0]);
                v.y = __uint_as_float(r[4 * q + 1]);
                v.z = __uint_as_float(r[4 * q + 2]);
                v.w = __uint_as_float(r[4 * q + 3]);
                *(float4*)(orow + base + 4 * q) = v;
            }
        }
    }
    asm volatile("tcgen05.fence::before_thread_sync;" ::: "memory");
    __syncthreads();
    cluster_sync();
    if (tid < 32) {
        asm volatile("tcgen05.relinquish_alloc_permit.cta_group::2.sync.aligned;");
        asm volatile("tcgen05.dealloc.cta_group::2.sync.aligned.b32 %0, %1;"
                     :: "r"(tmem), "r"(512u));
    }
    cluster_sync();
#else
    // ---------------- fallback: mma.sync (wait up front; no overlap, correct) ----------------
    gdc_wait();
    float* smf = (float*)dsm;
    const int m0 = blockIdx.x * 128;
    const int n0 = blockIdx.y * 512;
    const int wid = tid >> 5, lane = tid & 31;
    const int wm = wid >> 1, wn = wid & 1;
    const int NKT16 = NKT * 2;

    for (int nh = 0; nh < 4; nh++) {
        const int n0h = n0 + nh * 128;
        float c[2][8][4] = {};
#pragma unroll 1
        for (int s = 0; s < 2; s++) {
            int k0 = s * 16;
            const float* Ag = (k0 < KSPLIT) ? A0 + (size_t)m0 * LDA0 + k0
                                            : A1 + (size_t)m0 * LDA1 + (k0 - KSPLIT);
            int lda = (k0 < KSPLIT) ? LDA0 : LDA1;
            const float* Bg = (k0 < KSPLIT) ? B0 + (size_t)n0h * LDB0 + k0
                                            : B1 + (size_t)n0h * LDB1 + (k0 - KSPLIT);
            int ldb = (k0 < KSPLIT) ? LDB0 : LDB1;
            load_tile(smf + s * STAGE_FLOATS, Ag, lda);
            load_tile(smf + s * STAGE_FLOATS + 128 * SST, Bg, ldb);
            cp_commit();
        }
#pragma unroll 1
        for (int t = 0; t < NKT16; t++) {
            if (t + 2 < NKT16) cp_wait<1>(); else cp_wait<0>();
            __syncthreads();
            if (t + 2 < NKT16) {
                int k0 = (t + 2) * 16;
                float* sb = smf + ((t + 2) % 3) * STAGE_FLOATS;
                const float* Ag = (k0 < KSPLIT) ? A0 + (size_t)m0 * LDA0 + k0
                                                : A1 + (size_t)m0 * LDA1 + (k0 - KSPLIT);
                int lda = (k0 < KSPLIT) ? LDA0 : LDA1;
                const float* Bg = (k0 < KSPLIT) ? B0 + (size_t)n0h * LDB0 + k0
                                                : B1 + (size_t)n0h * LDB1 + (k0 - KSPLIT);
                int ldb = (k0 < KSPLIT) ? LDB0 : LDB1;
                load_tile(sb, Ag, lda);
                load_tile(sb + 128 * SST, Bg, ldb);
                cp_commit();
            }
            const float* st = smf + (t % 3) * STAGE_FLOATS;
            mma_tile(c, st, st + 128 * SST, wm, wn, lane);
        }
        __syncthreads();

        const int g = lane >> 2, tq = lane & 3;
#pragma unroll
        for (int mi = 0; mi < 2; mi++)
#pragma unroll
            for (int ni = 0; ni < 8; ni++) {
                int col = n0h + wn * 64 + ni * 8 + 2 * tq;
#pragma unroll
                for (int hf = 0; hf < 2; hf++) {
                    int row = m0 + wm * 32 + mi * 16 + hf * 8 + g;
                    float2 o;
                    o.x = c[mi][ni][hf * 2 + 0];
                    o.y = c[mi][ni][hf * 2 + 1];
                    *(float2*)(out + (size_t)row * ldOut + col) = o;
                }
            }
    }
#endif
}

// ---------------- launch ----------------
extern "C" void kernel_launch(void* const* d_in, const int* in_sizes, int n_in,
                              void* d_out, int out_size) {
    const float* x         = (const float*)d_in[0];
    const float* h_prev    = (const float*)d_in[1];
    const float* Br        = (const float*)d_in[2];
    const float* Bi        = (const float*)d_in[3];
    const float* Cr        = (const float*)d_in[4];
    const float* Ci        = (const float*)d_in[5];
    const float* v_log     = (const float*)d_in[6];
    const float* theta_log = (const float*)d_in[7];

    float *p_Crr, *p_Cir, *p_BrT, *p_BiTn, *p_E, *p_D;
    cudaGetSymbolAddress((void**)&p_Crr,  g_Crr);
    cudaGetSymbolAddress((void**)&p_Cir,  g_Cir);
    cudaGetSymbolAddress((void**)&p_BrT,  g_BrT);
    cudaGetSymbolAddress((void**)&p_BiTn, g_BiTn);
    cudaGetSymbolAddress((void**)&p_E,    g_E);
    cudaGetSymbolAddress((void**)&p_D,    g_D);

    // fold: E = [Cr|Ci] @ [BrT|-BiT]^T   (M=1024, N=1024, K=4096)
    auto* foldK = gemm_tc<128, 128, 2048, 2048, 2048, 2048, 2048, true>;
    // main: out = [hp|x] @ [D|E]^T       (K order: D-region first, E-region gated by PDL)
    auto* mainK = gemm_2cta<96, 2048, 2048, 1024, 2048, 1024>;

    const int smem_fold = 4 * (128 * 128 + 128 * 128) + 1024;   // 132 KB
    const int smem_main = 4 * (3 * 16384) + 1024;               // 197632 B
    cudaFuncSetAttribute(foldK, cudaFuncAttributeMaxDynamicSharedMemorySize, smem_fold);
    cudaFuncSetAttribute(mainK, cudaFuncAttributeMaxDynamicSharedMemorySize, smem_main);

    // launch 0: merged prep (transposes + Cr/Ci rounding + D)
    prep_all<<<10240, 256>>>(Br, Bi, (const float4*)Cr, (const float4*)Ci, v_log, theta_log);

    // launch 1: fold GEMM
    foldK<<<dim3(OUT_DIM / 128, IN_DIM / 128), 256, smem_fold>>>(p_Crr, p_Cir, p_BrT, p_BiTn,
                                                                 p_E, IN_DIM);

    // launch 2: main GEMM with PDL — starts during fold, gates on E via griddepcontrol.wait
    {
        cudaLaunchConfig_t cfg = {};
        cfg.gridDim = dim3(2 * (BQ / 256), OUT_DIM / 512);
        cfg.blockDim = dim3(256);
        cfg.dynamicSmemBytes = smem_main;
        cfg.stream = 0;
        cudaLaunchAttribute attrs[1];
        attrs[0].id = cudaLaunchAttributeProgrammaticStreamSerialization;
        attrs[0].val.programmaticStreamSerializationAllowed = 1;
        cfg.attrs = attrs;
        cfg.numAttrs = 1;
        cudaLaunchKernelEx(&cfg, mainK, h_prev, x, p_D, p_E, (float*)d_out, OUT_DIM);
    }
}